// round 2
// baseline (speedup 1.0000x reference)
#include <cuda_runtime.h>
#include <math.h>

#define Bsz  8
#define SEQ  1024
#define FEAT 768
#define NH   12
#define HD   64
#define BHN  (Bsz*NH)            // 96
#define LOG2E 1.4426950408889634f
#define LOGN  6.931471805599453f // log(1024)

// ---------------- scratch (static device allocations; no cudaMalloc) ----------------
__device__ float g_q[BHN*SEQ*HD];
__device__ float g_k[BHN*SEQ*HD];
__device__ float g_v[BHN*SEQ*HD];
__device__ float g_ctx[Bsz*SEQ*FEAT];
__device__ float g_u1[BHN*SEQ];
__device__ float g_v1[BHN*SEQ];
__device__ float g_lseC[BHN*SEQ];

// =====================================================================
// GEMM (NT): C[m,o] = sum_f A[m,f] * W[o,f]   (both row-major, contract f)
// mode 0: QKV — blockIdx.z selects Wq/Wk/Wv, scatter into [b,h,n,d]
// mode 1: out projection — adds bias, writes row-major [m, o]
// BM=BN=128, BK=8, 256 threads, 8x8 per thread.
// =====================================================================
__global__ void gemm_nt_kernel(const float* __restrict__ A,
                               const float* __restrict__ W0,
                               const float* __restrict__ W1,
                               const float* __restrict__ W2,
                               const float* __restrict__ bias,
                               float* __restrict__ Cout,
                               int mode)
{
    __shared__ float As[8*128];
    __shared__ float Bs[8*128];

    const float* W = W0;
    if (mode == 0) {
        if (blockIdx.z == 1) W = W1;
        else if (blockIdx.z == 2) W = W2;
    }

    int tid = threadIdx.x;
    int tx = tid & 15, ty = tid >> 4;
    int m0 = blockIdx.y * 128, n0 = blockIdx.x * 128;
    int lr = tid >> 1;            // 0..127
    int lk = (tid & 1) * 4;       // 0 or 4

    const float* Ap = A + (size_t)(m0 + lr) * FEAT + lk;
    const float* Bp = W + (size_t)(n0 + lr) * FEAT + lk;

    float acc[8][8];
#pragma unroll
    for (int i = 0; i < 8; i++)
#pragma unroll
        for (int j = 0; j < 8; j++) acc[i][j] = 0.f;

    for (int k0 = 0; k0 < FEAT; k0 += 8) {
        float4 av = *(const float4*)(Ap + k0);
        float4 bv = *(const float4*)(Bp + k0);
        __syncthreads();
        As[(lk+0)*128 + lr] = av.x; As[(lk+1)*128 + lr] = av.y;
        As[(lk+2)*128 + lr] = av.z; As[(lk+3)*128 + lr] = av.w;
        Bs[(lk+0)*128 + lr] = bv.x; Bs[(lk+1)*128 + lr] = bv.y;
        Bs[(lk+2)*128 + lr] = bv.z; Bs[(lk+3)*128 + lr] = bv.w;
        __syncthreads();
#pragma unroll
        for (int kk = 0; kk < 8; kk++) {
            float a[8], b[8];
#pragma unroll
            for (int i = 0; i < 8; i++) a[i] = As[kk*128 + ty*8 + i];
#pragma unroll
            for (int j = 0; j < 8; j++) b[j] = Bs[kk*128 + tx*8 + j];
#pragma unroll
            for (int i = 0; i < 8; i++)
#pragma unroll
                for (int j = 0; j < 8; j++)
                    acc[i][j] = fmaf(a[i], b[j], acc[i][j]);
        }
    }

    if (mode == 0) {
        float* outb = (blockIdx.z == 0) ? g_q : ((blockIdx.z == 1) ? g_k : g_v);
        int o0 = n0 + tx*8;
        int h  = o0 >> 6;
        int dd = o0 & 63;
#pragma unroll
        for (int i = 0; i < 8; i++) {
            int m = m0 + ty*8 + i;
            int b = m >> 10, nn = m & 1023;
            float* dst = outb + ((size_t)((b*NH + h)*SEQ + nn))*HD + dd;
#pragma unroll
            for (int j = 0; j < 8; j++) dst[j] = acc[i][j];
        }
    } else {
#pragma unroll
        for (int i = 0; i < 8; i++) {
            int m = m0 + ty*8 + i;
            float* dst = Cout + (size_t)m*FEAT + n0 + tx*8;
#pragma unroll
            for (int j = 0; j < 8; j++) dst[j] = acc[i][j] + bias[n0 + tx*8 + j];
        }
    }
}

// =====================================================================
// Streaming LSE over keys:
//   out[i] = alpha * LSE_j( (Q_i . K_j) * 0.125 + biasK[j] ) + beta
// Q,K: [BH, SEQ, HD]. One block per (bh, 128-row tile of i).
// =====================================================================
__global__ void lse_kernel(const float* __restrict__ Qg, const float* __restrict__ Kg,
                           const float* __restrict__ biasg, float* __restrict__ outg,
                           float alpha, float beta)
{
    extern __shared__ float sm[];
    float* Qs    = sm;                    // [64][129]
    float* Ks    = Qs + 64*129;           // [64][129]
    float* biasS = Ks + 64*129;           // [128]
    float* red   = biasS + 128;           // [128][33]

    int bh = blockIdx.y;
    int i0 = blockIdx.x * 128;
    int tid = threadIdx.x, tx = tid & 15, ty = tid >> 4;
    const float* Qbase = Qg + (size_t)bh*SEQ*HD;
    const float* Kbase = Kg + (size_t)bh*SEQ*HD;

    {   // load Q tile transposed: Qs[d][row]
        int d0 = (tid & 15) * 4, r = tid >> 4;
#pragma unroll
        for (int rr = 0; rr < 128; rr += 16) {
            float4 v = *(const float4*)(Qbase + (size_t)(i0 + rr + r)*HD + d0);
            Qs[(d0+0)*129 + rr + r] = v.x;
            Qs[(d0+1)*129 + rr + r] = v.y;
            Qs[(d0+2)*129 + rr + r] = v.z;
            Qs[(d0+3)*129 + rr + r] = v.w;
        }
    }

    float mr[8], sr[8];
#pragma unroll
    for (int i = 0; i < 8; i++) { mr[i] = -INFINITY; sr[i] = 0.f; }

    for (int jt = 0; jt < SEQ/128; jt++) {
        int j0 = jt * 128;
        __syncthreads();
        {
            int d0 = (tid & 15) * 4, r = tid >> 4;
#pragma unroll
            for (int rr = 0; rr < 128; rr += 16) {
                float4 v = *(const float4*)(Kbase + (size_t)(j0 + rr + r)*HD + d0);
                Ks[(d0+0)*129 + rr + r] = v.x;
                Ks[(d0+1)*129 + rr + r] = v.y;
                Ks[(d0+2)*129 + rr + r] = v.z;
                Ks[(d0+3)*129 + rr + r] = v.w;
            }
        }
        if (tid < 128) biasS[tid] = biasg ? biasg[(size_t)bh*SEQ + j0 + tid] : 0.f;
        __syncthreads();

        float accS[8][8];
#pragma unroll
        for (int i = 0; i < 8; i++)
#pragma unroll
            for (int j = 0; j < 8; j++) accS[i][j] = 0.f;

#pragma unroll 4
        for (int kk = 0; kk < 64; kk++) {
            float a[8], b[8];
#pragma unroll
            for (int i = 0; i < 8; i++) a[i] = Qs[kk*129 + ty*8 + i];
#pragma unroll
            for (int j = 0; j < 8; j++) b[j] = Ks[kk*129 + tx*8 + j];
#pragma unroll
            for (int i = 0; i < 8; i++)
#pragma unroll
                for (int j = 0; j < 8; j++)
                    accS[i][j] = fmaf(a[i], b[j], accS[i][j]);
        }

#pragma unroll
        for (int i = 0; i < 8; i++) {
            float vals[8];
            float vmax = -INFINITY;
#pragma unroll
            for (int j = 0; j < 8; j++) {
                vals[j] = accS[i][j] * 0.125f + biasS[tx*8 + j];
                vmax = fmaxf(vmax, vals[j]);
            }
            float nm = fmaxf(mr[i], vmax);
            float acc = sr[i] * exp2f((mr[i] - nm) * LOG2E);
#pragma unroll
            for (int j = 0; j < 8; j++) acc += exp2f((vals[j] - nm) * LOG2E);
            mr[i] = nm; sr[i] = acc;
        }
    }

    __syncthreads();
#pragma unroll
    for (int i = 0; i < 8; i++) {
        red[(ty*8 + i)*33 + tx*2 + 0] = mr[i];
        red[(ty*8 + i)*33 + tx*2 + 1] = sr[i];
    }
    __syncthreads();
    if (tid < 128) {
        float M = -INFINITY;
#pragma unroll
        for (int t = 0; t < 16; t++) M = fmaxf(M, red[tid*33 + t*2]);
        float S = 0.f;
#pragma unroll
        for (int t = 0; t < 16; t++)
            S += red[tid*33 + t*2 + 1] * exp2f((red[tid*33 + t*2] - M) * LOG2E);
        float lse = M + logf(S);
        outg[(size_t)bh*SEQ + i0 + tid] = alpha * lse + beta;
    }
}

// =====================================================================
// Pre-normalized attention * V:
//   ctx[b, i, h*64+d] = sum_j exp2f( ((q_i.k_j)*0.125 + v1[j] - lseC[i]) * LOG2E ) * v[j,d]
// lseC already contains + log(n), so this includes the 1/n factor.
// =====================================================================
__global__ void av_kernel()
{
    extern __shared__ float sm[];
    float* Qs    = sm;                   // [64][129]
    float* Ks    = Qs + 64*129;          // [64][129]
    float* Vs    = Ks + 64*129;          // [128][68]
    float* Ps    = Vs + 128*68;          // [128][129]   (Ps[j][i])
    float* biasS = Ps + 128*129;         // [128]
    float* lseS  = biasS + 128;          // [128]

    int bh = blockIdx.y;
    int b = bh / NH, h = bh % NH;
    int i0 = blockIdx.x * 128;
    int tid = threadIdx.x, tx = tid & 15, ty = tid >> 4;
    const float* Qbase = g_q + (size_t)bh*SEQ*HD;
    const float* Kbase = g_k + (size_t)bh*SEQ*HD;
    const float* Vbase = g_v + (size_t)bh*SEQ*HD;

    {   // Q tile transposed
        int d0 = (tid & 15) * 4, r = tid >> 4;
#pragma unroll
        for (int rr = 0; rr < 128; rr += 16) {
            float4 v = *(const float4*)(Qbase + (size_t)(i0 + rr + r)*HD + d0);
            Qs[(d0+0)*129 + rr + r] = v.x;
            Qs[(d0+1)*129 + rr + r] = v.y;
            Qs[(d0+2)*129 + rr + r] = v.z;
            Qs[(d0+3)*129 + rr + r] = v.w;
        }
    }
    if (tid < 128) lseS[tid] = g_lseC[(size_t)bh*SEQ + i0 + tid];

    float o[8][4];
#pragma unroll
    for (int i = 0; i < 8; i++)
#pragma unroll
        for (int d = 0; d < 4; d++) o[i][d] = 0.f;

    for (int jt = 0; jt < SEQ/128; jt++) {
        int j0 = jt * 128;
        __syncthreads();
        {
            int d0 = (tid & 15) * 4, r = tid >> 4;
#pragma unroll
            for (int rr = 0; rr < 128; rr += 16) {
                float4 v = *(const float4*)(Kbase + (size_t)(j0 + rr + r)*HD + d0);
                Ks[(d0+0)*129 + rr + r] = v.x;
                Ks[(d0+1)*129 + rr + r] = v.y;
                Ks[(d0+2)*129 + rr + r] = v.z;
                Ks[(d0+3)*129 + rr + r] = v.w;
                float4 vv = *(const float4*)(Vbase + (size_t)(j0 + rr + r)*HD + d0);
                *(float4*)(Vs + (rr + r)*68 + d0) = vv;
            }
        }
        if (tid < 128) biasS[tid] = g_v1[(size_t)bh*SEQ + j0 + tid];
        __syncthreads();

        float accS[8][8];
#pragma unroll
        for (int i = 0; i < 8; i++)
#pragma unroll
            for (int j = 0; j < 8; j++) accS[i][j] = 0.f;

#pragma unroll 4
        for (int kk = 0; kk < 64; kk++) {
            float a[8], bb[8];
#pragma unroll
            for (int i = 0; i < 8; i++) a[i] = Qs[kk*129 + ty*8 + i];
#pragma unroll
            for (int j = 0; j < 8; j++) bb[j] = Ks[kk*129 + tx*8 + j];
#pragma unroll
            for (int i = 0; i < 8; i++)
#pragma unroll
                for (int j = 0; j < 8; j++)
                    accS[i][j] = fmaf(a[i], bb[j], accS[i][j]);
        }

        // P = exp(s - lseC), stored transposed Ps[j][i]
#pragma unroll
        for (int i = 0; i < 8; i++) {
            float lc = lseS[ty*8 + i];
#pragma unroll
            for (int j = 0; j < 8; j++) {
                float s = accS[i][j] * 0.125f + biasS[tx*8 + j] - lc;
                Ps[(tx*8 + j)*129 + ty*8 + i] = exp2f(s * LOG2E);
            }
        }
        __syncthreads();

        // O += P @ V  (thread covers 8 rows x 4 dims)
#pragma unroll 4
        for (int jj = 0; jj < 128; jj++) {
            float a[8];
#pragma unroll
            for (int i = 0; i < 8; i++) a[i] = Ps[jj*129 + ty*8 + i];
            float4 bv = *(const float4*)(Vs + jj*68 + tx*4);
            float bb[4] = {bv.x, bv.y, bv.z, bv.w};
#pragma unroll
            for (int i = 0; i < 8; i++)
#pragma unroll
                for (int d = 0; d < 4; d++)
                    o[i][d] = fmaf(a[i], bb[d], o[i][d]);
        }
    }

    // write ctx in [b, n, h*64+d] layout for the output projection
#pragma unroll
    for (int i = 0; i < 8; i++) {
        int n = i0 + ty*8 + i;
        float* dst = g_ctx + ((size_t)(b*SEQ + n))*FEAT + h*HD + tx*4;
        *(float4*)dst = make_float4(o[i][0], o[i][1], o[i][2], o[i][3]);
    }
}

// =====================================================================
extern "C" void kernel_launch(void* const* d_in, const int* in_sizes, int n_in,
                              void* d_out, int out_size)
{
    const float* x  = (const float*)d_in[0];
    const float* Wq = (const float*)d_in[1];
    const float* Wk = (const float*)d_in[2];
    const float* Wv = (const float*)d_in[3];
    const float* Wo = (const float*)d_in[4];
    const float* bo = (const float*)d_in[5];
    float* out = (float*)d_out;

    const int lse_smem = (2*64*129 + 128 + 128*33) * 4;               // ~83.5 KB
    const int av_smem  = (2*64*129 + 128*68 + 128*129 + 256) * 4;     // ~168 KB
    cudaFuncSetAttribute(lse_kernel, cudaFuncAttributeMaxDynamicSharedMemorySize, lse_smem);
    cudaFuncSetAttribute(av_kernel,  cudaFuncAttributeMaxDynamicSharedMemorySize, av_smem);

    float *qp, *kp, *ctxp, *u1p, *v1p, *lcp;
    cudaGetSymbolAddress((void**)&qp,  g_q);
    cudaGetSymbolAddress((void**)&kp,  g_k);
    cudaGetSymbolAddress((void**)&ctxp, g_ctx);
    cudaGetSymbolAddress((void**)&u1p, g_u1);
    cudaGetSymbolAddress((void**)&v1p, g_v1);
    cudaGetSymbolAddress((void**)&lcp, g_lseC);

    // 1) QKV projection (one launch, z selects Wq/Wk/Wv)
    gemm_nt_kernel<<<dim3(FEAT/128, (Bsz*SEQ)/128, 3), 256>>>(x, Wq, Wk, Wv, nullptr, nullptr, 0);

    dim3 ag(SEQ/128, BHN);
    // 2) u1[i] = -log n - LSE_j(dots[i,j])
    lse_kernel<<<ag, 256, lse_smem>>>(qp, kp, nullptr, u1p, -1.f, -LOGN);
    // 3) v1[j] = -log n - LSE_i(dots[i,j] + u1[i])   (roles swapped)
    lse_kernel<<<ag, 256, lse_smem>>>(kp, qp, u1p, v1p, -1.f, -LOGN);
    // 4) lseC[i] = LSE_j(dots[i,j] + v1[j]) + log n
    lse_kernel<<<ag, 256, lse_smem>>>(qp, kp, v1p, lcp, 1.f, LOGN);
    // 5) ctx = exp(s - lseC) @ V
    av_kernel<<<ag, 256, av_smem>>>();
    // 6) out = ctx @ Wo^T + bo
    gemm_nt_kernel<<<dim3(FEAT/128, (Bsz*SEQ)/128, 1), 256>>>(ctxp, Wo, nullptr, nullptr, bo, out, 1);
}

// round 3
// speedup vs baseline: 4.3750x; 4.3750x over previous
#include <cuda_runtime.h>
#include <cuda_fp16.h>
#include <math.h>

#define Bsz  8
#define SEQ  1024
#define FEAT 768
#define NH   12
#define HD   64
#define BHN  (Bsz*NH)            // 96
#define LOG2E 1.4426950408889634f

// ---------------- static device scratch (no cudaMalloc) ----------------
__device__ __half g_P[(size_t)BHN*SEQ*SEQ];   // e^{dots}, fp16, 201MB
__device__ float  g_q[BHN*SEQ*HD];
__device__ float  g_k[BHN*SEQ*HD];
__device__ float  g_v[BHN*SEQ*HD];
__device__ __half g_xh[Bsz*SEQ*FEAT];
__device__ __half g_wh[4*FEAT*FEAT];          // Wq,Wk,Wv,Wo fp16
__device__ __half g_ctxh[Bsz*SEQ*FEAT];
__device__ float  g_r[BHN*SEQ];               // row sums of P
__device__ float  g_w[BHN*SEQ];               // e^{v1_j} = 1/c_j

// =====================================================================
// fp32 -> fp16 convert (vectorized)
// =====================================================================
__global__ void cvt_kernel(const float4* __restrict__ s, __half2* __restrict__ d, int n4)
{
    int i = blockIdx.x * 256 + threadIdx.x;
    if (i < n4) {
        float4 v = s[i];
        d[2*i+0] = __floats2half2_rn(v.x, v.y);
        d[2*i+1] = __floats2half2_rn(v.z, v.w);
    }
}

// =====================================================================
// fp16 tensor-core GEMM (NT): C[m,o] = sum_f A[m,f]*W[o,f], fp32 accum.
// mode 0: QKV (blockIdx.z selects W + q/k/v scatter target)
// mode 1: out projection + bias -> Cout row-major
// 128x128 tile, BK=32, 8 warps (4m x 2n), warp tile 32x64, mma m16n8k16.
// =====================================================================
__global__ void __launch_bounds__(256) gemm_h_kernel(
    const __half* __restrict__ A, const __half* __restrict__ Wbase,
    const float* __restrict__ bias, float* __restrict__ Cout, int mode)
{
    __shared__ __half As[128][40];
    __shared__ __half Bs[128][40];

    const __half* W = Wbase + (size_t)blockIdx.z * FEAT * FEAT;
    int tid = threadIdx.x;
    int m0 = blockIdx.y * 128, n0 = blockIdx.x * 128;
    int warp = tid >> 5, lane = tid & 31;
    int wm = (warp >> 1) * 32, wn = (warp & 1) * 64;
    int g = lane >> 2, t = lane & 3;

    int lrow = tid >> 2;            // 0..63
    int lcol = (tid & 3) * 8;       // 0,8,16,24

    float acc[2][8][4];
#pragma unroll
    for (int mi = 0; mi < 2; mi++)
#pragma unroll
        for (int ni = 0; ni < 8; ni++)
#pragma unroll
            for (int c = 0; c < 4; c++) acc[mi][ni][c] = 0.f;

    for (int k0 = 0; k0 < FEAT; k0 += 32) {
        __syncthreads();
        *(uint4*)&As[lrow][lcol]    = *(const uint4*)(A + (size_t)(m0+lrow)*FEAT    + k0 + lcol);
        *(uint4*)&As[lrow+64][lcol] = *(const uint4*)(A + (size_t)(m0+lrow+64)*FEAT + k0 + lcol);
        *(uint4*)&Bs[lrow][lcol]    = *(const uint4*)(W + (size_t)(n0+lrow)*FEAT    + k0 + lcol);
        *(uint4*)&Bs[lrow+64][lcol] = *(const uint4*)(W + (size_t)(n0+lrow+64)*FEAT + k0 + lcol);
        __syncthreads();
#pragma unroll
        for (int kk = 0; kk < 32; kk += 16) {
            unsigned a[2][4], b[8][2];
#pragma unroll
            for (int mi = 0; mi < 2; mi++) {
                int r0 = wm + mi*16 + g;
                a[mi][0] = *(const unsigned*)&As[r0  ][kk + 2*t];
                a[mi][1] = *(const unsigned*)&As[r0+8][kk + 2*t];
                a[mi][2] = *(const unsigned*)&As[r0  ][kk + 2*t + 8];
                a[mi][3] = *(const unsigned*)&As[r0+8][kk + 2*t + 8];
            }
#pragma unroll
            for (int ni = 0; ni < 8; ni++) {
                int c0 = wn + ni*8 + g;
                b[ni][0] = *(const unsigned*)&Bs[c0][kk + 2*t];
                b[ni][1] = *(const unsigned*)&Bs[c0][kk + 2*t + 8];
            }
#pragma unroll
            for (int mi = 0; mi < 2; mi++)
#pragma unroll
                for (int ni = 0; ni < 8; ni++) {
                    asm volatile(
                        "mma.sync.aligned.m16n8k16.row.col.f32.f16.f16.f32 "
                        "{%0,%1,%2,%3}, {%4,%5,%6,%7}, {%8,%9}, {%0,%1,%2,%3};\n"
                        : "+f"(acc[mi][ni][0]), "+f"(acc[mi][ni][1]),
                          "+f"(acc[mi][ni][2]), "+f"(acc[mi][ni][3])
                        : "r"(a[mi][0]), "r"(a[mi][1]), "r"(a[mi][2]), "r"(a[mi][3]),
                          "r"(b[ni][0]), "r"(b[ni][1]));
                }
        }
    }

#pragma unroll
    for (int mi = 0; mi < 2; mi++)
#pragma unroll
        for (int ni = 0; ni < 8; ni++)
#pragma unroll
            for (int ri = 0; ri < 2; ri++) {
                int m = m0 + wm + mi*16 + g + ri*8;
                int o = n0 + wn + ni*8 + 2*t;
                float v0 = acc[mi][ni][ri*2+0];
                float v1 = acc[mi][ni][ri*2+1];
                if (mode == 0) {
                    float* dst = (blockIdx.z == 0) ? g_q : (blockIdx.z == 1) ? g_k : g_v;
                    int b = m >> 10, nn = m & 1023, h = o >> 6, d = o & 63;
                    float* p = dst + ((size_t)((b*NH + h)*SEQ + nn))*HD + d;
                    p[0] = v0; p[1] = v1;
                } else {
                    float* p = Cout + (size_t)m * FEAT + o;
                    p[0] = v0 + bias[o]; p[1] = v1 + bias[o+1];
                }
            }
}

// =====================================================================
// Pass A: P = e^{dots} (fp16, stored), r_i = sum_j P_ij.
// Scalar QK (fp32), one exp per element. Block: 128 i-rows x 128 j tile loop.
// =====================================================================
__global__ void __launch_bounds__(256) passA_kernel()
{
    extern __shared__ float sm[];
    float* Qs  = sm;               // [64][129] transposed (d, i)
    float* Ks  = Qs + 64*129;      // [64][129]
    float* red = Ks + 64*129;      // [128][17]

    int bh = blockIdx.y;
    int i0 = blockIdx.x * 128;
    int tid = threadIdx.x, tx = tid & 15, ty = tid >> 4;
    const float* Qbase = g_q + (size_t)bh*SEQ*HD;
    const float* Kbase = g_k + (size_t)bh*SEQ*HD;
    __half* Pbase = g_P + ((size_t)bh << 20);

    {   // load Q tile transposed: Qs[d][row]
        int d0 = (tid & 15) * 4, r = tid >> 4;
#pragma unroll
        for (int rr = 0; rr < 128; rr += 16) {
            float4 v = *(const float4*)(Qbase + (size_t)(i0 + rr + r)*HD + d0);
            Qs[(d0+0)*129 + rr + r] = v.x;
            Qs[(d0+1)*129 + rr + r] = v.y;
            Qs[(d0+2)*129 + rr + r] = v.z;
            Qs[(d0+3)*129 + rr + r] = v.w;
        }
    }

    float rs[8];
#pragma unroll
    for (int i = 0; i < 8; i++) rs[i] = 0.f;

    const float CE = 0.125f * LOG2E;   // e^{0.125*dot} = 2^{dot*CE}

    for (int jt = 0; jt < SEQ/128; jt++) {
        int j0 = jt * 128;
        __syncthreads();
        {
            int d0 = (tid & 15) * 4, r = tid >> 4;
#pragma unroll
            for (int rr = 0; rr < 128; rr += 16) {
                float4 v = *(const float4*)(Kbase + (size_t)(j0 + rr + r)*HD + d0);
                Ks[(d0+0)*129 + rr + r] = v.x;
                Ks[(d0+1)*129 + rr + r] = v.y;
                Ks[(d0+2)*129 + rr + r] = v.z;
                Ks[(d0+3)*129 + rr + r] = v.w;
            }
        }
        __syncthreads();

        float accS[8][8];
#pragma unroll
        for (int i = 0; i < 8; i++)
#pragma unroll
            for (int j = 0; j < 8; j++) accS[i][j] = 0.f;

#pragma unroll 4
        for (int kk = 0; kk < 64; kk++) {
            float a[8], b[8];
#pragma unroll
            for (int i = 0; i < 8; i++) a[i] = Qs[kk*129 + ty*8 + i];
#pragma unroll
            for (int j = 0; j < 8; j++) b[j] = Ks[kk*129 + tx*8 + j];
#pragma unroll
            for (int i = 0; i < 8; i++)
#pragma unroll
                for (int j = 0; j < 8; j++)
                    accS[i][j] = fmaf(a[i], b[j], accS[i][j]);
        }

#pragma unroll
        for (int i = 0; i < 8; i++) {
            float p[8];
            float s = 0.f;
#pragma unroll
            for (int j = 0; j < 8; j++) {
                p[j] = exp2f(accS[i][j] * CE);
                s += p[j];
            }
            rs[i] += s;
            __align__(16) __half2 hh[4];
            hh[0] = __floats2half2_rn(p[0], p[1]);
            hh[1] = __floats2half2_rn(p[2], p[3]);
            hh[2] = __floats2half2_rn(p[4], p[5]);
            hh[3] = __floats2half2_rn(p[6], p[7]);
            *(uint4*)(Pbase + ((size_t)(i0 + ty*8 + i) << 10) + j0 + tx*8) = *(uint4*)hh;
        }
    }

    __syncthreads();
#pragma unroll
    for (int i = 0; i < 8; i++) red[(ty*8 + i)*17 + tx] = rs[i];
    __syncthreads();
    if (tid < 128) {
        float s = 0.f;
#pragma unroll
        for (int tt = 0; tt < 16; tt++) s += red[tid*17 + tt];
        g_r[(size_t)bh*SEQ + i0 + tid] = s;
    }
}

// =====================================================================
// Pass B: c_j = sum_i P_ij / r_i ;  w_j = 1/c_j  (= e^{v1_j}).
// Pure memory-bound column reduction. Grid (SEQ/256, BHN), 256 threads.
// =====================================================================
__global__ void __launch_bounds__(256) passB_kernel()
{
    __shared__ float rinv[SEQ];
    int bh = blockIdx.y;
    int tid = threadIdx.x;
    int j = blockIdx.x * 256 + tid;

    for (int i = tid; i < SEQ; i += 256)
        rinv[i] = 1.f / g_r[(size_t)bh*SEQ + i];
    __syncthreads();

    const __half* Pp = g_P + ((size_t)bh << 20) + j;
    float c = 0.f;
#pragma unroll 8
    for (int i = 0; i < SEQ; i++)
        c += __half2float(Pp[(size_t)i << 10]) * rinv[i];

    g_w[(size_t)bh*SEQ + j] = 1.f / c;
}

// =====================================================================
// Pass C: out_i = (1/n) * (sum_j P_ij w_j v_j) / (sum_j P_ij w_j)
// Reads stored P (no exp, no QK). Writes ctx as fp16 for the out-proj GEMM.
// =====================================================================
__global__ void __launch_bounds__(256) passC_kernel()
{
    extern __shared__ float sm[];
    float* Ps = sm;                // [128][132]  (i, j), already * w_j
    float* Vs = Ps + 128*132;      // [128][68]
    float* ws = Vs + 128*68;       // [128]

    int bh = blockIdx.y;
    int b = bh / NH, h = bh % NH;
    int i0 = blockIdx.x * 128;
    int tid = threadIdx.x, tx = tid & 15, ty = tid >> 4;
    const float* Vbase = g_v + (size_t)bh*SEQ*HD;
    const __half* Pbase = g_P + ((size_t)bh << 20);

    float o[8][4], s[8];
#pragma unroll
    for (int i = 0; i < 8; i++) {
        s[i] = 0.f;
#pragma unroll
        for (int d = 0; d < 4; d++) o[i][d] = 0.f;
    }

    for (int jt = 0; jt < SEQ/128; jt++) {
        int j0 = jt * 128;
        __syncthreads();
        if (tid < 128) ws[tid] = g_w[(size_t)bh*SEQ + j0 + tid];
        {
            int d0 = (tid & 15) * 4, r = tid >> 4;
#pragma unroll
            for (int rr = 0; rr < 128; rr += 16)
                *(float4*)(Vs + (rr + r)*68 + d0) =
                    *(const float4*)(Vbase + (size_t)(j0 + rr + r)*HD + d0);
        }
        __syncthreads();
        {
            int r = tid >> 4, c0 = (tid & 15) * 8;
#pragma unroll
            for (int rr = 0; rr < 128; rr += 16) {
                uint4 u = *(const uint4*)(Pbase + ((size_t)(i0 + rr + r) << 10) + j0 + c0);
                __half2* hp = (__half2*)&u;
                float* dst = Ps + (rr + r)*132 + c0;
                float2 f0 = __half22float2(hp[0]);
                float2 f1 = __half22float2(hp[1]);
                float2 f2 = __half22float2(hp[2]);
                float2 f3 = __half22float2(hp[3]);
                dst[0] = f0.x * ws[c0+0]; dst[1] = f0.y * ws[c0+1];
                dst[2] = f1.x * ws[c0+2]; dst[3] = f1.y * ws[c0+3];
                dst[4] = f2.x * ws[c0+4]; dst[5] = f2.y * ws[c0+5];
                dst[6] = f3.x * ws[c0+6]; dst[7] = f3.y * ws[c0+7];
            }
        }
        __syncthreads();

#pragma unroll 2
        for (int jj = 0; jj < 128; jj++) {
            float a[8];
#pragma unroll
            for (int i = 0; i < 8; i++) a[i] = Ps[(ty*8 + i)*132 + jj];
            float4 bv = *(const float4*)(Vs + jj*68 + tx*4);
#pragma unroll
            for (int i = 0; i < 8; i++) {
                o[i][0] = fmaf(a[i], bv.x, o[i][0]);
                o[i][1] = fmaf(a[i], bv.y, o[i][1]);
                o[i][2] = fmaf(a[i], bv.z, o[i][2]);
                o[i][3] = fmaf(a[i], bv.w, o[i][3]);
                s[i] += a[i];
            }
        }
    }

    const float inv_n = 1.f / (float)SEQ;
#pragma unroll
    for (int i = 0; i < 8; i++) {
        int n = i0 + ty*8 + i;
        float is = inv_n / s[i];
        __half* dst = g_ctxh + ((size_t)(b*SEQ + n))*FEAT + h*HD + tx*4;
        __half2 h0 = __floats2half2_rn(o[i][0]*is, o[i][1]*is);
        __half2 h1 = __floats2half2_rn(o[i][2]*is, o[i][3]*is);
        *(__half2*)(dst + 0) = h0;
        *(__half2*)(dst + 2) = h1;
    }
}

// =====================================================================
extern "C" void kernel_launch(void* const* d_in, const int* in_sizes, int n_in,
                              void* d_out, int out_size)
{
    const float* x  = (const float*)d_in[0];
    const float* Wq = (const float*)d_in[1];
    const float* Wk = (const float*)d_in[2];
    const float* Wv = (const float*)d_in[3];
    const float* Wo = (const float*)d_in[4];
    const float* bo = (const float*)d_in[5];
    float* out = (float*)d_out;

    const int passA_smem = (2*64*129 + 128*17) * 4;              // ~74.8 KB
    const int passC_smem = (128*132 + 128*68 + 128) * 4;         // ~100.5 KB
    cudaFuncSetAttribute(passA_kernel, cudaFuncAttributeMaxDynamicSharedMemorySize, passA_smem);
    cudaFuncSetAttribute(passC_kernel, cudaFuncAttributeMaxDynamicSharedMemorySize, passC_smem);

    __half *xh, *wh, *ctxh;
    cudaGetSymbolAddress((void**)&xh,   g_xh);
    cudaGetSymbolAddress((void**)&wh,   g_wh);
    cudaGetSymbolAddress((void**)&ctxh, g_ctxh);

    // 0) fp32 -> fp16 copies of x and the four weight matrices
    {
        int nx4 = Bsz*SEQ*FEAT/4;     // 1572864
        int nw4 = FEAT*FEAT/4;        // 147456
        cvt_kernel<<<(nx4+255)/256, 256>>>((const float4*)x,  (__half2*)xh, nx4);
        cvt_kernel<<<(nw4+255)/256, 256>>>((const float4*)Wq, (__half2*)(wh + 0*FEAT*FEAT), nw4);
        cvt_kernel<<<(nw4+255)/256, 256>>>((const float4*)Wk, (__half2*)(wh + 1*FEAT*FEAT), nw4);
        cvt_kernel<<<(nw4+255)/256, 256>>>((const float4*)Wv, (__half2*)(wh + 2*FEAT*FEAT), nw4);
        cvt_kernel<<<(nw4+255)/256, 256>>>((const float4*)Wo, (__half2*)(wh + 3*FEAT*FEAT), nw4);
    }

    // 1) QKV projection (tensor cores, z selects Wq/Wk/Wv)
    gemm_h_kernel<<<dim3(FEAT/128, (Bsz*SEQ)/128, 3), 256>>>(xh, wh, nullptr, nullptr, 0);

    // 2) P = e^{dots} (fp16) + row sums r
    passA_kernel<<<dim3(SEQ/128, BHN), 256, passA_smem>>>();

    // 3) w_j = 1 / sum_i(P_ij / r_i)
    passB_kernel<<<dim3(SEQ/256, BHN), 256>>>();

    // 4) ctx = (1/n) * row-normalized (P*diag(w)) @ V   (fp16 ctx)
    passC_kernel<<<dim3(SEQ/128, BHN), 256, passC_smem>>>();

    // 5) out = ctx @ Wo^T + bo (tensor cores)
    gemm_h_kernel<<<dim3(FEAT/128, (Bsz*SEQ)/128, 1), 256>>>(
        ctxh, wh + (size_t)3*FEAT*FEAT, bo, out, 1);
}

// round 4
// speedup vs baseline: 7.3160x; 1.6722x over previous
#include <cuda_runtime.h>
#include <cuda_fp16.h>
#include <math.h>

#define Bsz  8
#define SEQ  1024
#define FEAT 768
#define NH   12
#define HD   64
#define BHN  (Bsz*NH)            // 96
#define LOG2E 1.4426950408889634f

// ---------------- static device scratch (no cudaMalloc) ----------------
__device__ __half g_P[(size_t)BHN*SEQ*SEQ];   // e^{dots}, fp16, 201MB
__device__ __half g_qh[BHN*SEQ*HD];
__device__ __half g_kh[BHN*SEQ*HD];
__device__ __half g_vh[BHN*SEQ*HD];
__device__ __half g_xh[Bsz*SEQ*FEAT];
__device__ __half g_wh[4*FEAT*FEAT];          // Wq,Wk,Wv,Wo fp16
__device__ __half g_ctxh[Bsz*SEQ*FEAT];
__device__ float  g_r[BHN*SEQ];               // row sums of P
__device__ float  g_w[BHN*SEQ];               // e^{v1_j} = 1/c_j

// =====================================================================
// fp32 -> fp16 convert (vectorized)
// =====================================================================
__global__ void cvt_kernel(const float4* __restrict__ s, __half2* __restrict__ d, int n4)
{
    int i = blockIdx.x * 256 + threadIdx.x;
    if (i < n4) {
        float4 v = s[i];
        d[2*i+0] = __floats2half2_rn(v.x, v.y);
        d[2*i+1] = __floats2half2_rn(v.z, v.w);
    }
}

// =====================================================================
// fp16 tensor-core GEMM (NT): C[m,o] = sum_f A[m,f]*W[o,f], fp32 accum.
// mode 0: QKV (blockIdx.z selects W; writes fp16 q/k/v in [b,h,n,d])
// mode 1: out projection + bias -> Cout row-major fp32
// =====================================================================
__global__ void __launch_bounds__(256) gemm_h_kernel(
    const __half* __restrict__ A, const __half* __restrict__ Wbase,
    const float* __restrict__ bias, float* __restrict__ Cout, int mode)
{
    __shared__ __half As[128][40];
    __shared__ __half Bs[128][40];

    const __half* W = Wbase + (size_t)blockIdx.z * FEAT * FEAT;
    int tid = threadIdx.x;
    int m0 = blockIdx.y * 128, n0 = blockIdx.x * 128;
    int warp = tid >> 5, lane = tid & 31;
    int wm = (warp >> 1) * 32, wn = (warp & 1) * 64;
    int g = lane >> 2, t = lane & 3;

    int lrow = tid >> 2;            // 0..63
    int lcol = (tid & 3) * 8;       // 0,8,16,24

    float acc[2][8][4];
#pragma unroll
    for (int mi = 0; mi < 2; mi++)
#pragma unroll
        for (int ni = 0; ni < 8; ni++)
#pragma unroll
            for (int c = 0; c < 4; c++) acc[mi][ni][c] = 0.f;

    for (int k0 = 0; k0 < FEAT; k0 += 32) {
        __syncthreads();
        *(uint4*)&As[lrow][lcol]    = *(const uint4*)(A + (size_t)(m0+lrow)*FEAT    + k0 + lcol);
        *(uint4*)&As[lrow+64][lcol] = *(const uint4*)(A + (size_t)(m0+lrow+64)*FEAT + k0 + lcol);
        *(uint4*)&Bs[lrow][lcol]    = *(const uint4*)(W + (size_t)(n0+lrow)*FEAT    + k0 + lcol);
        *(uint4*)&Bs[lrow+64][lcol] = *(const uint4*)(W + (size_t)(n0+lrow+64)*FEAT + k0 + lcol);
        __syncthreads();
#pragma unroll
        for (int kk = 0; kk < 32; kk += 16) {
            unsigned a[2][4], b[8][2];
#pragma unroll
            for (int mi = 0; mi < 2; mi++) {
                int r0 = wm + mi*16 + g;
                a[mi][0] = *(const unsigned*)&As[r0  ][kk + 2*t];
                a[mi][1] = *(const unsigned*)&As[r0+8][kk + 2*t];
                a[mi][2] = *(const unsigned*)&As[r0  ][kk + 2*t + 8];
                a[mi][3] = *(const unsigned*)&As[r0+8][kk + 2*t + 8];
            }
#pragma unroll
            for (int ni = 0; ni < 8; ni++) {
                int c0 = wn + ni*8 + g;
                b[ni][0] = *(const unsigned*)&Bs[c0][kk + 2*t];
                b[ni][1] = *(const unsigned*)&Bs[c0][kk + 2*t + 8];
            }
#pragma unroll
            for (int mi = 0; mi < 2; mi++)
#pragma unroll
                for (int ni = 0; ni < 8; ni++) {
                    asm volatile(
                        "mma.sync.aligned.m16n8k16.row.col.f32.f16.f16.f32 "
                        "{%0,%1,%2,%3}, {%4,%5,%6,%7}, {%8,%9}, {%0,%1,%2,%3};\n"
                        : "+f"(acc[mi][ni][0]), "+f"(acc[mi][ni][1]),
                          "+f"(acc[mi][ni][2]), "+f"(acc[mi][ni][3])
                        : "r"(a[mi][0]), "r"(a[mi][1]), "r"(a[mi][2]), "r"(a[mi][3]),
                          "r"(b[ni][0]), "r"(b[ni][1]));
                }
        }
    }

#pragma unroll
    for (int mi = 0; mi < 2; mi++)
#pragma unroll
        for (int ni = 0; ni < 8; ni++)
#pragma unroll
            for (int ri = 0; ri < 2; ri++) {
                int m = m0 + wm + mi*16 + g + ri*8;
                int o = n0 + wn + ni*8 + 2*t;
                float v0 = acc[mi][ni][ri*2+0];
                float v1 = acc[mi][ni][ri*2+1];
                if (mode == 0) {
                    __half* dst = (blockIdx.z == 0) ? g_qh : (blockIdx.z == 1) ? g_kh : g_vh;
                    int b = m >> 10, nn = m & 1023, h = o >> 6, d = o & 63;
                    *(__half2*)(dst + ((size_t)((b*NH + h)*SEQ + nn))*HD + d) =
                        __floats2half2_rn(v0, v1);
                } else {
                    float* p = Cout + (size_t)m * FEAT + o;
                    p[0] = v0 + bias[o]; p[1] = v1 + bias[o+1];
                }
            }
}

// =====================================================================
// Pass A (tensor core): P = e^{dots/8} fp16 stored; r_i = sum_j P_ij.
// Block: 128 i-rows; loop over 8 j-tiles of 128. 8 warps (4m x 2n).
// =====================================================================
__global__ void __launch_bounds__(256) passA_kernel()
{
    __shared__ __half Qs[128][72];
    __shared__ __half Ks[128][72];
    __shared__ float red[128][2];

    int bh = blockIdx.y;
    int i0 = blockIdx.x * 128;
    int tid = threadIdx.x;
    int warp = tid >> 5, lane = tid & 31;
    int g = lane >> 2, t = lane & 3;
    int wm = (warp >> 1) * 32, wn = (warp & 1) * 64;
    const __half* Qb = g_qh + (size_t)bh*SEQ*HD;
    const __half* Kb = g_kh + (size_t)bh*SEQ*HD;
    __half* Pb = g_P + ((size_t)bh << 20);

    int lr = tid >> 1, lc = (tid & 1) * 32;
    {
        const __half* src = Qb + (size_t)(i0 + lr)*HD + lc;
        *(uint4*)&Qs[lr][lc+0]  = *(const uint4*)(src+0);
        *(uint4*)&Qs[lr][lc+8]  = *(const uint4*)(src+8);
        *(uint4*)&Qs[lr][lc+16] = *(const uint4*)(src+16);
        *(uint4*)&Qs[lr][lc+24] = *(const uint4*)(src+24);
    }

    float rs[2][2];
    rs[0][0] = rs[0][1] = rs[1][0] = rs[1][1] = 0.f;
    const float CE = 0.125f * LOG2E;

    for (int jt = 0; jt < 8; jt++) {
        int j0 = jt * 128;
        __syncthreads();
        {
            const __half* src = Kb + (size_t)(j0 + lr)*HD + lc;
            *(uint4*)&Ks[lr][lc+0]  = *(const uint4*)(src+0);
            *(uint4*)&Ks[lr][lc+8]  = *(const uint4*)(src+8);
            *(uint4*)&Ks[lr][lc+16] = *(const uint4*)(src+16);
            *(uint4*)&Ks[lr][lc+24] = *(const uint4*)(src+24);
        }
        __syncthreads();

        float acc[2][8][4];
#pragma unroll
        for (int mi = 0; mi < 2; mi++)
#pragma unroll
            for (int ni = 0; ni < 8; ni++)
#pragma unroll
                for (int c = 0; c < 4; c++) acc[mi][ni][c] = 0.f;

#pragma unroll
        for (int kk = 0; kk < 64; kk += 16) {
            unsigned a[2][4], b[8][2];
#pragma unroll
            for (int mi = 0; mi < 2; mi++) {
                int r0 = wm + mi*16 + g;
                a[mi][0] = *(const unsigned*)&Qs[r0  ][kk + 2*t];
                a[mi][1] = *(const unsigned*)&Qs[r0+8][kk + 2*t];
                a[mi][2] = *(const unsigned*)&Qs[r0  ][kk + 2*t + 8];
                a[mi][3] = *(const unsigned*)&Qs[r0+8][kk + 2*t + 8];
            }
#pragma unroll
            for (int ni = 0; ni < 8; ni++) {
                int c0 = wn + ni*8 + g;
                b[ni][0] = *(const unsigned*)&Ks[c0][kk + 2*t];
                b[ni][1] = *(const unsigned*)&Ks[c0][kk + 2*t + 8];
            }
#pragma unroll
            for (int mi = 0; mi < 2; mi++)
#pragma unroll
                for (int ni = 0; ni < 8; ni++) {
                    asm volatile(
                        "mma.sync.aligned.m16n8k16.row.col.f32.f16.f16.f32 "
                        "{%0,%1,%2,%3}, {%4,%5,%6,%7}, {%8,%9}, {%0,%1,%2,%3};\n"
                        : "+f"(acc[mi][ni][0]), "+f"(acc[mi][ni][1]),
                          "+f"(acc[mi][ni][2]), "+f"(acc[mi][ni][3])
                        : "r"(a[mi][0]), "r"(a[mi][1]), "r"(a[mi][2]), "r"(a[mi][3]),
                          "r"(b[ni][0]), "r"(b[ni][1]));
                }
        }

        // epilogue: exp, store fp16 P, accumulate row sums
#pragma unroll
        for (int mi = 0; mi < 2; mi++)
#pragma unroll
            for (int ri = 0; ri < 2; ri++) {
                int row = i0 + wm + mi*16 + g + ri*8;
                float sum = 0.f;
#pragma unroll
                for (int ni = 0; ni < 8; ni++) {
                    float p0 = exp2f(acc[mi][ni][ri*2+0] * CE);
                    float p1 = exp2f(acc[mi][ni][ri*2+1] * CE);
                    sum += p0 + p1;
                    *(__half2*)(Pb + ((size_t)row << 10) + j0 + wn + ni*8 + 2*t) =
                        __floats2half2_rn(p0, p1);
                }
                rs[mi][ri] += sum;
            }
    }

    // row-sum reduction: 4 lanes (t) -> smem across the 2 n-warps
#pragma unroll
    for (int mi = 0; mi < 2; mi++)
#pragma unroll
        for (int ri = 0; ri < 2; ri++) {
            float v = rs[mi][ri];
            v += __shfl_xor_sync(0xffffffffu, v, 1);
            v += __shfl_xor_sync(0xffffffffu, v, 2);
            if (t == 0) red[wm + mi*16 + g + ri*8][warp & 1] = v;
        }
    __syncthreads();
    if (tid < 128)
        g_r[(size_t)bh*SEQ + i0 + tid] = red[tid][0] + red[tid][1];
}

// =====================================================================
// Pass B: c_j = sum_i P_ij / r_i ;  w_j = 1/c_j.  Memory-bound.
// =====================================================================
__global__ void __launch_bounds__(256) passB_kernel()
{
    __shared__ float rinv[SEQ];
    int bh = blockIdx.y;
    int tid = threadIdx.x;
    int j = blockIdx.x * 256 + tid;

    for (int i = tid; i < SEQ; i += 256)
        rinv[i] = 1.f / g_r[(size_t)bh*SEQ + i];
    __syncthreads();

    const __half* Pp = g_P + ((size_t)bh << 20) + j;
    float c = 0.f;
#pragma unroll 8
    for (int i = 0; i < SEQ; i++)
        c += __half2float(Pp[(size_t)i << 10]) * rinv[i];

    g_w[(size_t)bh*SEQ + j] = 1.f / c;
}

// =====================================================================
// Pass C (tensor core): out_i = (1/n) * (sum_j P_ij w_j v_j) / (sum_j P_ij w_j)
// A = P*diag(w) fp16 (scaled in smem), B = V^T with ones row at d=64 (n=72)
// so the denominator falls out of mma column 64. 8 warps, 16 i-rows each.
// =====================================================================
__global__ void __launch_bounds__(256) passC_kernel()
{
    extern __shared__ __half smh[];
    __half (*Ps)[136] = (__half (*)[136])smh;                 // [128][136]
    __half (*Vs)[136] = (__half (*)[136])(smh + 128*136);     // [72][136]
    __half2* ws2 = (__half2*)(smh + 128*136 + 72*136);        // [64]

    int bh = blockIdx.y;
    int b = bh / NH, h = bh % NH;
    int i0 = blockIdx.x * 128;
    int tid = threadIdx.x;
    int warp = tid >> 5, lane = tid & 31;
    int g = lane >> 2, t = lane & 3;
    int wm = warp * 16;

    const __half* Vb = g_vh + (size_t)bh*SEQ*HD;
    const __half* Pb = g_P + ((size_t)bh << 20);
    const float* wg = g_w + (size_t)bh*SEQ;

    float acc[9][4];
#pragma unroll
    for (int ni = 0; ni < 9; ni++)
#pragma unroll
        for (int c = 0; c < 4; c++) acc[ni][c] = 0.f;

    int pr = tid >> 1, pc = (tid & 1) * 64;

    for (int jt = 0; jt < 8; jt++) {
        int j0 = jt * 128;
        __syncthreads();   // prev mma done reading Ps/Vs

        if (tid < 64)
            ws2[tid] = __floats2half2_rn(wg[j0 + 2*tid], wg[j0 + 2*tid + 1]);
        {   // V transpose into Vs[d][j] + ones row 64, zeros 65..71
            int j = tid & 127, d0 = (tid >> 7) * 32;
#pragma unroll
            for (int dd = 0; dd < 16; dd++) {
                __half2 v = *(const __half2*)(Vb + (size_t)(j0 + j)*HD + d0 + 2*dd);
                Vs[d0 + 2*dd    ][j] = __low2half(v);
                Vs[d0 + 2*dd + 1][j] = __high2half(v);
            }
        }
        if (tid < 128) {
            Vs[64][tid] = __float2half(1.f);
#pragma unroll
            for (int r = 65; r < 72; r++) Vs[r][tid] = __float2half(0.f);
        }
        __syncthreads();   // ws2 + Vs visible

        {   // load P tile, scale by w_j, store to Ps
            const __half* src = Pb + ((size_t)(i0 + pr) << 10) + j0 + pc;
#pragma unroll
            for (int c = 0; c < 8; c++) {
                uint4 u = *(const uint4*)(src + 8*c);
                __half2* hp = (__half2*)&u;
                int wb = (pc >> 1) + 4*c;
                hp[0] = __hmul2(hp[0], ws2[wb+0]);
                hp[1] = __hmul2(hp[1], ws2[wb+1]);
                hp[2] = __hmul2(hp[2], ws2[wb+2]);
                hp[3] = __hmul2(hp[3], ws2[wb+3]);
                *(uint4*)&Ps[pr][pc + 8*c] = u;
            }
        }
        __syncthreads();   // Ps visible

#pragma unroll
        for (int kk = 0; kk < 128; kk += 16) {
            unsigned a[4], bfr[9][2];
            a[0] = *(const unsigned*)&Ps[wm + g    ][kk + 2*t];
            a[1] = *(const unsigned*)&Ps[wm + g + 8][kk + 2*t];
            a[2] = *(const unsigned*)&Ps[wm + g    ][kk + 2*t + 8];
            a[3] = *(const unsigned*)&Ps[wm + g + 8][kk + 2*t + 8];
#pragma unroll
            for (int ni = 0; ni < 9; ni++) {
                bfr[ni][0] = *(const unsigned*)&Vs[ni*8 + g][kk + 2*t];
                bfr[ni][1] = *(const unsigned*)&Vs[ni*8 + g][kk + 2*t + 8];
            }
#pragma unroll
            for (int ni = 0; ni < 9; ni++) {
                asm volatile(
                    "mma.sync.aligned.m16n8k16.row.col.f32.f16.f16.f32 "
                    "{%0,%1,%2,%3}, {%4,%5,%6,%7}, {%8,%9}, {%0,%1,%2,%3};\n"
                    : "+f"(acc[ni][0]), "+f"(acc[ni][1]),
                      "+f"(acc[ni][2]), "+f"(acc[ni][3])
                    : "r"(a[0]), "r"(a[1]), "r"(a[2]), "r"(a[3]),
                      "r"(bfr[ni][0]), "r"(bfr[ni][1]));
            }
        }
    }

    // epilogue: broadcast row sums (col 64, held by t==0 lanes in n-tile 8)
    const float inv_n = 1.f / (float)SEQ;
    int src = lane & ~3;
    float s0 = __shfl_sync(0xffffffffu, acc[8][0], src);
    float s1 = __shfl_sync(0xffffffffu, acc[8][2], src);
    float is0 = inv_n / s0, is1 = inv_n / s1;

    int row0 = i0 + wm + g, row1 = row0 + 8;
#pragma unroll
    for (int ni = 0; ni < 8; ni++) {
        int col = h*HD + ni*8 + 2*t;
        *(__half2*)(g_ctxh + ((size_t)(b*SEQ + row0))*FEAT + col) =
            __floats2half2_rn(acc[ni][0]*is0, acc[ni][1]*is0);
        *(__half2*)(g_ctxh + ((size_t)(b*SEQ + row1))*FEAT + col) =
            __floats2half2_rn(acc[ni][2]*is1, acc[ni][3]*is1);
    }
}

// =====================================================================
extern "C" void kernel_launch(void* const* d_in, const int* in_sizes, int n_in,
                              void* d_out, int out_size)
{
    const float* x  = (const float*)d_in[0];
    const float* Wq = (const float*)d_in[1];
    const float* Wk = (const float*)d_in[2];
    const float* Wv = (const float*)d_in[3];
    const float* Wo = (const float*)d_in[4];
    const float* bo = (const float*)d_in[5];
    float* out = (float*)d_out;

    const int passC_smem = (128*136 + 72*136) * 2 + 64 * 4;   // ~54.7 KB
    cudaFuncSetAttribute(passC_kernel, cudaFuncAttributeMaxDynamicSharedMemorySize, passC_smem);

    __half *xh, *wh, *ctxh;
    cudaGetSymbolAddress((void**)&xh,   g_xh);
    cudaGetSymbolAddress((void**)&wh,   g_wh);
    cudaGetSymbolAddress((void**)&ctxh, g_ctxh);

    // 0) fp32 -> fp16 copies of x and the four weight matrices
    {
        int nx4 = Bsz*SEQ*FEAT/4;
        int nw4 = FEAT*FEAT/4;
        cvt_kernel<<<(nx4+255)/256, 256>>>((const float4*)x,  (__half2*)xh, nx4);
        cvt_kernel<<<(nw4+255)/256, 256>>>((const float4*)Wq, (__half2*)(wh + 0*FEAT*FEAT), nw4);
        cvt_kernel<<<(nw4+255)/256, 256>>>((const float4*)Wk, (__half2*)(wh + 1*FEAT*FEAT), nw4);
        cvt_kernel<<<(nw4+255)/256, 256>>>((const float4*)Wv, (__half2*)(wh + 2*FEAT*FEAT), nw4);
        cvt_kernel<<<(nw4+255)/256, 256>>>((const float4*)Wo, (__half2*)(wh + 3*FEAT*FEAT), nw4);
    }

    // 1) QKV projection (tensor cores) -> fp16 q/k/v
    gemm_h_kernel<<<dim3(FEAT/128, (Bsz*SEQ)/128, 3), 256>>>(xh, wh, nullptr, nullptr, 0);

    // 2) P = e^{dots} (fp16) + row sums r  (tensor-core QK^T)
    passA_kernel<<<dim3(SEQ/128, BHN), 256>>>();

    // 3) w_j = 1 / sum_i(P_ij / r_i)
    passB_kernel<<<dim3(SEQ/256, BHN), 256>>>();

    // 4) ctx = (1/n) * row-normalized (P*diag(w)) @ [V | 1]  (tensor-core)
    passC_kernel<<<dim3(SEQ/128, BHN), 256, passC_smem>>>();

    // 5) out = ctx @ Wo^T + bo (tensor cores)
    gemm_h_kernel<<<dim3(FEAT/128, (Bsz*SEQ)/128, 1), 256>>>(
        ctxh, wh + (size_t)3*FEAT*FEAT, bo, out, 1);
}

// round 5
// speedup vs baseline: 7.9736x; 1.0899x over previous
#include <cuda_runtime.h>
#include <cuda_fp16.h>
#include <math.h>

#define Bsz  8
#define SEQ  1024
#define FEAT 768
#define NH   12
#define HD   64
#define BHN  (Bsz*NH)            // 96
#define LOG2E 1.4426950408889634f

// ---------------- static device scratch (no cudaMalloc) ----------------
__device__ __half g_qh[BHN*SEQ*HD];
__device__ __half g_kh[BHN*SEQ*HD];
__device__ __half g_vh[BHN*SEQ*HD];
__device__ __half g_xh[Bsz*SEQ*FEAT];
__device__ __half g_wh[4*FEAT*FEAT];          // Wq,Wk,Wv,Wo fp16
__device__ __half g_ctxh[Bsz*SEQ*FEAT];
__device__ float  g_r[BHN*SEQ];               // r_i = sum_j e^{dots_ij}
__device__ float  g_w[BHN*SEQ];               // w_j = e^{v1_j}

// ---------------- helpers ----------------
__device__ __forceinline__ unsigned sptr(const void* p) {
    unsigned r;
    asm("{ .reg .u64 t; cvta.to.shared.u64 t, %1; cvt.u32.u64 %0, t; }"
        : "=r"(r) : "l"(p));
    return r;
}
#define CPA16(dst, src) \
    asm volatile("cp.async.ca.shared.global [%0], [%1], 16;\n" :: "r"(dst), "l"(src))
#define CPCOMMIT() asm volatile("cp.async.commit_group;\n")
#define CPWAIT(n)  asm volatile("cp.async.wait_group %0;\n" :: "n"(n))

__device__ __forceinline__ void mma_f16(float* c, const unsigned* a, const unsigned* b) {
    asm volatile(
        "mma.sync.aligned.m16n8k16.row.col.f32.f16.f16.f32 "
        "{%0,%1,%2,%3}, {%4,%5,%6,%7}, {%8,%9}, {%0,%1,%2,%3};\n"
        : "+f"(c[0]), "+f"(c[1]), "+f"(c[2]), "+f"(c[3])
        : "r"(a[0]), "r"(a[1]), "r"(a[2]), "r"(a[3]), "r"(b[0]), "r"(b[1]));
}

// =====================================================================
// fp32 -> fp16 converts
// =====================================================================
__global__ void cvt_kernel(const float4* __restrict__ s, __half2* __restrict__ d, int n4)
{
    int i = blockIdx.x * 256 + threadIdx.x;
    if (i < n4) {
        float4 v = s[i];
        d[2*i+0] = __floats2half2_rn(v.x, v.y);
        d[2*i+1] = __floats2half2_rn(v.z, v.w);
    }
}

__global__ void cvtW_kernel(const float4* __restrict__ s0, const float4* __restrict__ s1,
                            const float4* __restrict__ s2, const float4* __restrict__ s3,
                            __half2* __restrict__ d, int n4)
{
    const float4* s = (blockIdx.y == 0) ? s0 : (blockIdx.y == 1) ? s1
                    : (blockIdx.y == 2) ? s2 : s3;
    __half2* dd = d + (size_t)blockIdx.y * n4 * 2;
    int i = blockIdx.x * 256 + threadIdx.x;
    if (i < n4) {
        float4 v = s[i];
        dd[2*i+0] = __floats2half2_rn(v.x, v.y);
        dd[2*i+1] = __floats2half2_rn(v.z, v.w);
    }
}

// =====================================================================
// Pipelined fp16 tensor-core GEMM (NT): C[m,o] = sum_f A[m,f]*W[o,f].
// 3-stage cp.async, 128x128 tile, BK=32, 8 warps (4m x 2n).
// mode 0: QKV (z selects W; writes fp16 q/k/v in [b,h,n,d])
// mode 1: out projection + bias -> fp32 row-major
// =====================================================================
#define GSTG (128*40)
__global__ void __launch_bounds__(256) gemm_h_kernel(
    const __half* __restrict__ A, const __half* __restrict__ Wbase,
    const float* __restrict__ bias, float* __restrict__ Cout, int mode)
{
    extern __shared__ __half gsm[];   // As[3][128][40] | Bs[3][128][40]

    const __half* W = Wbase + (size_t)blockIdx.z * FEAT * FEAT;
    int tid = threadIdx.x;
    int m0 = blockIdx.y * 128, n0 = blockIdx.x * 128;
    int warp = tid >> 5, lane = tid & 31;
    int wm = (warp >> 1) * 32, wn = (warp & 1) * 64;
    int g = lane >> 2, t = lane & 3;

    auto load_stage = [&](int s, int k0) {
        __half* As = gsm + s * GSTG;
        __half* Bs = gsm + 3*GSTG + s * GSTG;
#pragma unroll
        for (int q = 0; q < 2; q++) {
            int c = tid*2 + q;
            int row = c >> 2, off = (c & 3) * 8;
            CPA16(sptr(As + row*40 + off), A + (size_t)(m0+row)*FEAT + k0 + off);
            CPA16(sptr(Bs + row*40 + off), W + (size_t)(n0+row)*FEAT + k0 + off);
        }
    };

#pragma unroll
    for (int s = 0; s < 3; s++) { load_stage(s, s*32); CPCOMMIT(); }

    float acc[2][8][4];
#pragma unroll
    for (int mi = 0; mi < 2; mi++)
#pragma unroll
        for (int ni = 0; ni < 8; ni++)
#pragma unroll
            for (int c = 0; c < 4; c++) acc[mi][ni][c] = 0.f;

    const int NT = FEAT / 32;   // 24
    for (int kt = 0; kt < NT; kt++) {
        CPWAIT(2); __syncthreads();
        int st = kt % 3;
        const __half* As = gsm + st * GSTG;
        const __half* Bs = gsm + 3*GSTG + st * GSTG;
#pragma unroll
        for (int kk = 0; kk < 32; kk += 16) {
            unsigned a[2][4], b[8][2];
#pragma unroll
            for (int mi = 0; mi < 2; mi++) {
                int r0 = wm + mi*16 + g;
                a[mi][0] = *(const unsigned*)(As + (r0  )*40 + kk + 2*t);
                a[mi][1] = *(const unsigned*)(As + (r0+8)*40 + kk + 2*t);
                a[mi][2] = *(const unsigned*)(As + (r0  )*40 + kk + 2*t + 8);
                a[mi][3] = *(const unsigned*)(As + (r0+8)*40 + kk + 2*t + 8);
            }
#pragma unroll
            for (int ni = 0; ni < 8; ni++) {
                int c0 = wn + ni*8 + g;
                b[ni][0] = *(const unsigned*)(Bs + c0*40 + kk + 2*t);
                b[ni][1] = *(const unsigned*)(Bs + c0*40 + kk + 2*t + 8);
            }
#pragma unroll
            for (int mi = 0; mi < 2; mi++)
#pragma unroll
                for (int ni = 0; ni < 8; ni++)
                    mma_f16(acc[mi][ni], a[mi], b[ni]);
        }
        __syncthreads();
        if (kt + 3 < NT) load_stage(st, (kt+3)*32);
        CPCOMMIT();
    }

#pragma unroll
    for (int mi = 0; mi < 2; mi++)
#pragma unroll
        for (int ni = 0; ni < 8; ni++)
#pragma unroll
            for (int ri = 0; ri < 2; ri++) {
                int m = m0 + wm + mi*16 + g + ri*8;
                int o = n0 + wn + ni*8 + 2*t;
                float v0 = acc[mi][ni][ri*2+0];
                float v1 = acc[mi][ni][ri*2+1];
                if (mode == 0) {
                    __half* dst = (blockIdx.z == 0) ? g_qh : (blockIdx.z == 1) ? g_kh : g_vh;
                    int b = m >> 10, nn = m & 1023, h = o >> 6, d = o & 63;
                    *(__half2*)(dst + ((size_t)((b*NH + h)*SEQ + nn))*HD + d) =
                        __floats2half2_rn(v0, v1);
                } else {
                    float* p = Cout + (size_t)m * FEAT + o;
                    p[0] = v0 + bias[o]; p[1] = v1 + bias[o+1];
                }
            }
}

// =====================================================================
// passR: outv[row] = f( sum_col exp(A_row . B_col / 8) * wcol )
// wcol = 1/colw[col] if colw else 1;  out = 1/sum if recip else sum.
// passA: (q, k, null, g_r, 0)    -> r_i
// passB: (k, q, g_r,  g_w, 1)    -> w_j
// 2-stage cp.async on the B (column) tiles.
// =====================================================================
__global__ void __launch_bounds__(256) passR_kernel(
    const __half* __restrict__ Ag, const __half* __restrict__ Bg,
    const float* __restrict__ colw, float* __restrict__ outv, int recip)
{
    extern __shared__ __half sh[];
    __half (*Qs)[72] = (__half (*)[72])sh;                  // [128][72]
    __half* KsB = sh + 128*72;                              // [2][128][72]
    float* wcol = (float*)(sh + 128*72 + 2*128*72);         // [128]
    float* red  = wcol + 128;                               // [128][2]

    int bh = blockIdx.y, i0 = blockIdx.x * 128;
    int tid = threadIdx.x;
    int warp = tid >> 5, lane = tid & 31;
    int g = lane >> 2, t = lane & 3;
    int wm = (warp >> 1) * 32, wn = (warp & 1) * 64;
    const __half* Ab = Ag + (size_t)bh*SEQ*HD;
    const __half* Bb = Bg + (size_t)bh*SEQ*HD;
    const float* cw = colw ? colw + (size_t)bh*SEQ : (const float*)0;

    {   // A tile once
        int lr = tid >> 1, lc = (tid & 1) * 32;
        const __half* src = Ab + (size_t)(i0 + lr)*HD + lc;
        *(uint4*)&Qs[lr][lc+0]  = *(const uint4*)(src+0);
        *(uint4*)&Qs[lr][lc+8]  = *(const uint4*)(src+8);
        *(uint4*)&Qs[lr][lc+16] = *(const uint4*)(src+16);
        *(uint4*)&Qs[lr][lc+24] = *(const uint4*)(src+24);
    }

    auto loadK = [&](int s, int j0) {
        __half* Ks = KsB + s * 128*72;
#pragma unroll
        for (int q = 0; q < 4; q++) {
            int c = tid*4 + q;
            int row = c >> 3, off = (c & 7) * 8;
            CPA16(sptr(Ks + row*72 + off), Bb + (size_t)(j0+row)*HD + off);
        }
    };
    loadK(0, 0);   CPCOMMIT();
    loadK(1, 128); CPCOMMIT();

    float rs[2][2] = {{0.f,0.f},{0.f,0.f}};
    const float CE = 0.125f * LOG2E;

    for (int jt = 0; jt < 8; jt++) {
        int j0 = jt * 128, st = jt & 1;
        const __half* Ks = KsB + st * 128*72;
        CPWAIT(1); __syncthreads();

        float wraw = 1.f;
        if (cw && tid < 128) wraw = cw[j0 + tid];   // early LDG, hidden by mma

        float acc[2][8][4];
#pragma unroll
        for (int mi = 0; mi < 2; mi++)
#pragma unroll
            for (int ni = 0; ni < 8; ni++)
#pragma unroll
                for (int c = 0; c < 4; c++) acc[mi][ni][c] = 0.f;

#pragma unroll
        for (int kk = 0; kk < 64; kk += 16) {
            unsigned a[2][4], b[8][2];
#pragma unroll
            for (int mi = 0; mi < 2; mi++) {
                int r0 = wm + mi*16 + g;
                a[mi][0] = *(const unsigned*)(&Qs[r0  ][kk + 2*t]);
                a[mi][1] = *(const unsigned*)(&Qs[r0+8][kk + 2*t]);
                a[mi][2] = *(const unsigned*)(&Qs[r0  ][kk + 2*t + 8]);
                a[mi][3] = *(const unsigned*)(&Qs[r0+8][kk + 2*t + 8]);
            }
#pragma unroll
            for (int ni = 0; ni < 8; ni++) {
                int c0 = wn + ni*8 + g;
                b[ni][0] = *(const unsigned*)(Ks + c0*72 + kk + 2*t);
                b[ni][1] = *(const unsigned*)(Ks + c0*72 + kk + 2*t + 8);
            }
#pragma unroll
            for (int mi = 0; mi < 2; mi++)
#pragma unroll
                for (int ni = 0; ni < 8; ni++)
                    mma_f16(acc[mi][ni], a[mi], b[ni]);
        }

        if (tid < 128) wcol[tid] = cw ? (1.f / wraw) : 1.f;
        __syncthreads();

#pragma unroll
        for (int mi = 0; mi < 2; mi++)
#pragma unroll
            for (int ri = 0; ri < 2; ri++) {
                float sum = 0.f;
#pragma unroll
                for (int ni = 0; ni < 8; ni++) {
                    int c0 = wn + ni*8 + 2*t;
                    float p0 = exp2f(acc[mi][ni][ri*2+0] * CE) * wcol[c0];
                    float p1 = exp2f(acc[mi][ni][ri*2+1] * CE) * wcol[c0+1];
                    sum += p0 + p1;
                }
                rs[mi][ri] += sum;
            }

        if (jt + 2 < 8) loadK(st, (jt+2)*128);
        CPCOMMIT();
    }

#pragma unroll
    for (int mi = 0; mi < 2; mi++)
#pragma unroll
        for (int ri = 0; ri < 2; ri++) {
            float v = rs[mi][ri];
            v += __shfl_xor_sync(0xffffffffu, v, 1);
            v += __shfl_xor_sync(0xffffffffu, v, 2);
            if (t == 0) red[(wm + mi*16 + g + ri*8)*2 + (warp & 1)] = v;
        }
    __syncthreads();
    if (tid < 128) {
        float s = red[tid*2] + red[tid*2 + 1];
        outv[(size_t)bh*SEQ + i0 + tid] = recip ? (1.f / s) : s;
    }
}

// =====================================================================
// passC (flash-style): out_i = (1/n) (sum_j e^{dots} w_j v_j) / (sum_j e^{dots} w_j)
// S mma -> exp*w in registers -> repack accumulator as A-fragment -> O mma.
// 8 warps x 16 rows; K tiles 2-stage cp.async; V transposed behind S mma.
// =====================================================================
__global__ void __launch_bounds__(256) passC_kernel()
{
    extern __shared__ __half sh[];
    __half (*Qs)[72] = (__half (*)[72])sh;                  // [128][72]
    __half* KsB = sh + 128*72;                              // [2][128][72]
    __half (*Vs)[136] = (__half (*)[136])(sh + 3*128*72);   // [64][136] V^T
    float* wsm = (float*)(sh + 3*128*72 + 64*136);          // [128]

    int bh = blockIdx.y;
    int b = bh / NH, h = bh % NH;
    int i0 = blockIdx.x * 128;
    int tid = threadIdx.x;
    int warp = tid >> 5, lane = tid & 31;
    int g = lane >> 2, t = lane & 3;
    int wm = warp * 16;

    const __half* Qb = g_qh + (size_t)bh*SEQ*HD;
    const __half* Kb = g_kh + (size_t)bh*SEQ*HD;
    const __half* Vb = g_vh + (size_t)bh*SEQ*HD;
    const float* wg = g_w + (size_t)bh*SEQ;

    {   // Q tile once
        int lr = tid >> 1, lc = (tid & 1) * 32;
        const __half* src = Qb + (size_t)(i0 + lr)*HD + lc;
        *(uint4*)&Qs[lr][lc+0]  = *(const uint4*)(src+0);
        *(uint4*)&Qs[lr][lc+8]  = *(const uint4*)(src+8);
        *(uint4*)&Qs[lr][lc+16] = *(const uint4*)(src+16);
        *(uint4*)&Qs[lr][lc+24] = *(const uint4*)(src+24);
    }

    auto loadK = [&](int s, int j0) {
        __half* Ks = KsB + s * 128*72;
#pragma unroll
        for (int q = 0; q < 4; q++) {
            int c = tid*4 + q;
            int row = c >> 3, off = (c & 7) * 8;
            CPA16(sptr(Ks + row*72 + off), Kb + (size_t)(j0+row)*HD + off);
        }
    };
    loadK(0, 0);   CPCOMMIT();
    loadK(1, 128); CPCOMMIT();

    float oacc[8][4];
#pragma unroll
    for (int nd = 0; nd < 8; nd++)
#pragma unroll
        for (int c = 0; c < 4; c++) oacc[nd][c] = 0.f;
    float den0 = 0.f, den1 = 0.f;
    const float CE = 0.125f * LOG2E;

    int vj = tid & 127, vd0 = (tid >> 7) * 32;

    for (int jt = 0; jt < 8; jt++) {
        int j0 = jt * 128, st = jt & 1;
        const __half* Ks = KsB + st * 128*72;
        CPWAIT(1); __syncthreads();   // Ks[st] ready; prev O-mma done with Vs

        // early global loads (latency hidden behind S mma)
        __half2 vreg[16];
#pragma unroll
        for (int dd = 0; dd < 16; dd++)
            vreg[dd] = *(const __half2*)(Vb + (size_t)(j0 + vj)*HD + vd0 + 2*dd);
        float wraw = 0.f;
        if (tid < 128) wraw = wg[j0 + tid];

        // S = Q K^T  (16 rows x 128 cols per warp)
        float sacc[16][4];
#pragma unroll
        for (int ni = 0; ni < 16; ni++)
#pragma unroll
            for (int c = 0; c < 4; c++) sacc[ni][c] = 0.f;

#pragma unroll
        for (int kk = 0; kk < 64; kk += 16) {
            unsigned a[4];
            a[0] = *(const unsigned*)(&Qs[wm + g    ][kk + 2*t]);
            a[1] = *(const unsigned*)(&Qs[wm + g + 8][kk + 2*t]);
            a[2] = *(const unsigned*)(&Qs[wm + g    ][kk + 2*t + 8]);
            a[3] = *(const unsigned*)(&Qs[wm + g + 8][kk + 2*t + 8]);
#pragma unroll
            for (int ni = 0; ni < 16; ni++) {
                unsigned bb[2];
                bb[0] = *(const unsigned*)(Ks + (ni*8 + g)*72 + kk + 2*t);
                bb[1] = *(const unsigned*)(Ks + (ni*8 + g)*72 + kk + 2*t + 8);
                mma_f16(sacc[ni], a, bb);
            }
        }

        // stage V^T + w into smem
#pragma unroll
        for (int dd = 0; dd < 16; dd++) {
            Vs[vd0 + 2*dd    ][vj] = __low2half(vreg[dd]);
            Vs[vd0 + 2*dd + 1][vj] = __high2half(vreg[dd]);
        }
        if (tid < 128) wsm[tid] = wraw;
        __syncthreads();   // Vs/wsm visible; all warps past S mma

        // P = exp(S)*w, accumulate den, repack as A fragments
        unsigned aP[8][4];
#pragma unroll
        for (int ni = 0; ni < 16; ni++) {
            int c0 = ni*8 + 2*t;
            float w0 = wsm[c0], w1 = wsm[c0+1];
            float p0 = exp2f(sacc[ni][0] * CE) * w0;
            float p1 = exp2f(sacc[ni][1] * CE) * w1;
            float p2 = exp2f(sacc[ni][2] * CE) * w0;
            float p3 = exp2f(sacc[ni][3] * CE) * w1;
            den0 += p0 + p1; den1 += p2 + p3;
            __half2 h01 = __floats2half2_rn(p0, p1);
            __half2 h23 = __floats2half2_rn(p2, p3);
            int kc = ni >> 1;
            if ((ni & 1) == 0) {
                aP[kc][0] = *(unsigned*)&h01; aP[kc][1] = *(unsigned*)&h23;
            } else {
                aP[kc][2] = *(unsigned*)&h01; aP[kc][3] = *(unsigned*)&h23;
            }
        }

        // O += P @ V^T
#pragma unroll
        for (int kc = 0; kc < 8; kc++) {
#pragma unroll
            for (int nd = 0; nd < 8; nd++) {
                unsigned bb[2];
                bb[0] = *(const unsigned*)(&Vs[nd*8 + g][kc*16 + 2*t]);
                bb[1] = *(const unsigned*)(&Vs[nd*8 + g][kc*16 + 2*t + 8]);
                mma_f16(oacc[nd], aP[kc], bb);
            }
        }
        __syncthreads();   // O mma done before Vs/Ks[st] overwritten

        if (jt + 2 < 8) loadK(st, (jt+2)*128);
        CPCOMMIT();
    }

    // normalize + write ctx (fp16, [b, n, h*64+d])
    den0 += __shfl_xor_sync(0xffffffffu, den0, 1);
    den0 += __shfl_xor_sync(0xffffffffu, den0, 2);
    den1 += __shfl_xor_sync(0xffffffffu, den1, 1);
    den1 += __shfl_xor_sync(0xffffffffu, den1, 2);
    const float inv_n = 1.f / (float)SEQ;
    float is0 = inv_n / den0, is1 = inv_n / den1;

    int row0 = i0 + wm + g, row1 = row0 + 8;
#pragma unroll
    for (int nd = 0; nd < 8; nd++) {
        int col = h*HD + nd*8 + 2*t;
        *(__half2*)(g_ctxh + ((size_t)(b*SEQ + row0))*FEAT + col) =
            __floats2half2_rn(oacc[nd][0]*is0, oacc[nd][1]*is0);
        *(__half2*)(g_ctxh + ((size_t)(b*SEQ + row1))*FEAT + col) =
            __floats2half2_rn(oacc[nd][2]*is1, oacc[nd][3]*is1);
    }
}

// =====================================================================
extern "C" void kernel_launch(void* const* d_in, const int* in_sizes, int n_in,
                              void* d_out, int out_size)
{
    const float* x  = (const float*)d_in[0];
    const float* Wq = (const float*)d_in[1];
    const float* Wk = (const float*)d_in[2];
    const float* Wv = (const float*)d_in[3];
    const float* Wo = (const float*)d_in[4];
    const float* bo = (const float*)d_in[5];
    float* out = (float*)d_out;

    const int gemm_smem  = 6 * GSTG * 2;                                  // 61440
    const int passR_smem = (128*72 + 2*128*72) * 2 + 128*4 + 256*4;       // 56832
    const int passC_smem = (3*128*72) * 2 + 64*136*2 + 128*4;             // 73216
    cudaFuncSetAttribute(gemm_h_kernel, cudaFuncAttributeMaxDynamicSharedMemorySize, gemm_smem);
    cudaFuncSetAttribute(passR_kernel,  cudaFuncAttributeMaxDynamicSharedMemorySize, passR_smem);
    cudaFuncSetAttribute(passC_kernel,  cudaFuncAttributeMaxDynamicSharedMemorySize, passC_smem);

    __half *xh, *wh, *ctxh, *qp, *kp;
    float *rp, *wp;
    cudaGetSymbolAddress((void**)&xh,   g_xh);
    cudaGetSymbolAddress((void**)&wh,   g_wh);
    cudaGetSymbolAddress((void**)&ctxh, g_ctxh);
    cudaGetSymbolAddress((void**)&qp,   g_qh);
    cudaGetSymbolAddress((void**)&kp,   g_kh);
    cudaGetSymbolAddress((void**)&rp,   g_r);
    cudaGetSymbolAddress((void**)&wp,   g_w);

    // 0) fp32 -> fp16 copies
    {
        int nx4 = Bsz*SEQ*FEAT/4;
        int nw4 = FEAT*FEAT/4;
        cvt_kernel<<<(nx4+255)/256, 256>>>((const float4*)x, (__half2*)xh, nx4);
        cvtW_kernel<<<dim3((nw4+255)/256, 4), 256>>>(
            (const float4*)Wq, (const float4*)Wk, (const float4*)Wv, (const float4*)Wo,
            (__half2*)wh, nw4);
    }

    // 1) QKV projection -> fp16 q/k/v
    gemm_h_kernel<<<dim3(FEAT/128, (Bsz*SEQ)/128, 3), 256, gemm_smem>>>(
        xh, wh, nullptr, nullptr, 0);

    dim3 ag(SEQ/128, BHN);
    // 2) r_i = sum_j e^{dots_ij}
    passR_kernel<<<ag, 256, passR_smem>>>(qp, kp, nullptr, rp, 0);
    // 3) w_j = 1 / sum_i e^{dots_ij} / r_i
    passR_kernel<<<ag, 256, passR_smem>>>(kp, qp, rp, wp, 1);
    // 4) ctx (flash-style, register P)
    passC_kernel<<<ag, 256, passC_smem>>>();
    // 5) out = ctx @ Wo^T + bo
    gemm_h_kernel<<<dim3(FEAT/128, (Bsz*SEQ)/128, 1), 256, gemm_smem>>>(
        ctxh, wh + (size_t)3*FEAT*FEAT, bo, out, 1);
}

// round 6
// speedup vs baseline: 10.0771x; 1.2638x over previous
#include <cuda_runtime.h>
#include <cuda_fp16.h>
#include <math.h>

#define Bsz  8
#define SEQ  1024
#define FEAT 768
#define NH   12
#define HD   64
#define BHN  (Bsz*NH)            // 96
#define LOG2E 1.4426950408889634f
#define QSCL 0.1803368801111204f // 0.125 * log2(e)

// ---------------- static device scratch (no cudaMalloc) ----------------
__device__ __half g_qh[BHN*SEQ*HD];           // pre-scaled by QSCL
__device__ __half g_kh[BHN*SEQ*HD];
__device__ __half g_vh[BHN*SEQ*HD];
__device__ __half g_xh[Bsz*SEQ*FEAT];
__device__ __half g_wh[4*FEAT*FEAT];          // Wq,Wk,Wv,Wo fp16
__device__ __half g_ctxh[Bsz*SEQ*FEAT];
__device__ float  g_r[BHN*SEQ];               // r_i = sum_j e^{dots_ij}
__device__ float  g_w[BHN*SEQ];               // w_j = e^{v1_j}

// ---------------- helpers ----------------
__device__ __forceinline__ unsigned sptr(const void* p) {
    unsigned r;
    asm("{ .reg .u64 t; cvta.to.shared.u64 t, %1; cvt.u32.u64 %0, t; }"
        : "=r"(r) : "l"(p));
    return r;
}
#define CPA16(dst, src) \
    asm volatile("cp.async.ca.shared.global [%0], [%1], 16;\n" :: "r"(dst), "l"(src))
#define CPCOMMIT() asm volatile("cp.async.commit_group;\n")
#define CPWAIT(n)  asm volatile("cp.async.wait_group %0;\n" :: "n"(n))

__device__ __forceinline__ void mma_f16(float* c, const unsigned* a, const unsigned* b) {
    asm volatile(
        "mma.sync.aligned.m16n8k16.row.col.f32.f16.f16.f32 "
        "{%0,%1,%2,%3}, {%4,%5,%6,%7}, {%8,%9}, {%0,%1,%2,%3};\n"
        : "+f"(c[0]), "+f"(c[1]), "+f"(c[2]), "+f"(c[3])
        : "r"(a[0]), "r"(a[1]), "r"(a[2]), "r"(a[3]), "r"(b[0]), "r"(b[1]));
}

__device__ __forceinline__ void ldsm_x2_t(unsigned& r0, unsigned& r1, unsigned addr) {
    asm volatile("ldmatrix.sync.aligned.m8n8.x2.trans.shared.b16 {%0,%1}, [%2];\n"
        : "=r"(r0), "=r"(r1) : "r"(addr));
}

// =====================================================================
// fp32 -> fp16 converts
// =====================================================================
__global__ void cvt_kernel(const float4* __restrict__ s, __half2* __restrict__ d, int n4)
{
    int i = blockIdx.x * 256 + threadIdx.x;
    if (i < n4) {
        float4 v = s[i];
        d[2*i+0] = __floats2half2_rn(v.x, v.y);
        d[2*i+1] = __floats2half2_rn(v.z, v.w);
    }
}

__global__ void cvtW_kernel(const float4* __restrict__ s0, const float4* __restrict__ s1,
                            const float4* __restrict__ s2, const float4* __restrict__ s3,
                            __half2* __restrict__ d, int n4)
{
    const float4* s = (blockIdx.y == 0) ? s0 : (blockIdx.y == 1) ? s1
                    : (blockIdx.y == 2) ? s2 : s3;
    __half2* dd = d + (size_t)blockIdx.y * n4 * 2;
    int i = blockIdx.x * 256 + threadIdx.x;
    if (i < n4) {
        float4 v = s[i];
        dd[2*i+0] = __floats2half2_rn(v.x, v.y);
        dd[2*i+1] = __floats2half2_rn(v.z, v.w);
    }
}

// =====================================================================
// Pipelined fp16 tensor-core GEMM (NT): C[m,o] = sum_f A[m,f]*W[o,f].
// 3-stage cp.async, 128x128 tile, BK=32, 8 warps (4m x 2n).
// mode 0: QKV (z selects W; q output pre-scaled by QSCL)
// mode 1: out projection + bias -> fp32 row-major
// =====================================================================
#define GSTG (128*40)
__global__ void __launch_bounds__(256) gemm_h_kernel(
    const __half* __restrict__ A, const __half* __restrict__ Wbase,
    const float* __restrict__ bias, float* __restrict__ Cout, int mode)
{
    extern __shared__ __half gsm[];   // As[3][128][40] | Bs[3][128][40]

    const __half* W = Wbase + (size_t)blockIdx.z * FEAT * FEAT;
    int tid = threadIdx.x;
    int m0 = blockIdx.y * 128, n0 = blockIdx.x * 128;
    int warp = tid >> 5, lane = tid & 31;
    int wm = (warp >> 1) * 32, wn = (warp & 1) * 64;
    int g = lane >> 2, t = lane & 3;

    auto load_stage = [&](int s, int k0) {
        __half* As = gsm + s * GSTG;
        __half* Bs = gsm + 3*GSTG + s * GSTG;
#pragma unroll
        for (int q = 0; q < 2; q++) {
            int c = tid*2 + q;
            int row = c >> 2, off = (c & 3) * 8;
            CPA16(sptr(As + row*40 + off), A + (size_t)(m0+row)*FEAT + k0 + off);
            CPA16(sptr(Bs + row*40 + off), W + (size_t)(n0+row)*FEAT + k0 + off);
        }
    };

#pragma unroll
    for (int s = 0; s < 3; s++) { load_stage(s, s*32); CPCOMMIT(); }

    float acc[2][8][4];
#pragma unroll
    for (int mi = 0; mi < 2; mi++)
#pragma unroll
        for (int ni = 0; ni < 8; ni++)
#pragma unroll
            for (int c = 0; c < 4; c++) acc[mi][ni][c] = 0.f;

    const int NT = FEAT / 32;   // 24
    for (int kt = 0; kt < NT; kt++) {
        CPWAIT(2); __syncthreads();
        int st = kt % 3;
        const __half* As = gsm + st * GSTG;
        const __half* Bs = gsm + 3*GSTG + st * GSTG;
#pragma unroll
        for (int kk = 0; kk < 32; kk += 16) {
            unsigned a[2][4], b[8][2];
#pragma unroll
            for (int mi = 0; mi < 2; mi++) {
                int r0 = wm + mi*16 + g;
                a[mi][0] = *(const unsigned*)(As + (r0  )*40 + kk + 2*t);
                a[mi][1] = *(const unsigned*)(As + (r0+8)*40 + kk + 2*t);
                a[mi][2] = *(const unsigned*)(As + (r0  )*40 + kk + 2*t + 8);
                a[mi][3] = *(const unsigned*)(As + (r0+8)*40 + kk + 2*t + 8);
            }
#pragma unroll
            for (int ni = 0; ni < 8; ni++) {
                int c0 = wn + ni*8 + g;
                b[ni][0] = *(const unsigned*)(Bs + c0*40 + kk + 2*t);
                b[ni][1] = *(const unsigned*)(Bs + c0*40 + kk + 2*t + 8);
            }
#pragma unroll
            for (int mi = 0; mi < 2; mi++)
#pragma unroll
                for (int ni = 0; ni < 8; ni++)
                    mma_f16(acc[mi][ni], a[mi], b[ni]);
        }
        __syncthreads();
        if (kt + 3 < NT) load_stage(st, (kt+3)*32);
        CPCOMMIT();
    }

    float scl = (mode == 0 && blockIdx.z == 0) ? QSCL : 1.f;
#pragma unroll
    for (int mi = 0; mi < 2; mi++)
#pragma unroll
        for (int ni = 0; ni < 8; ni++)
#pragma unroll
            for (int ri = 0; ri < 2; ri++) {
                int m = m0 + wm + mi*16 + g + ri*8;
                int o = n0 + wn + ni*8 + 2*t;
                float v0 = acc[mi][ni][ri*2+0] * scl;
                float v1 = acc[mi][ni][ri*2+1] * scl;
                if (mode == 0) {
                    __half* dst = (blockIdx.z == 0) ? g_qh : (blockIdx.z == 1) ? g_kh : g_vh;
                    int b = m >> 10, nn = m & 1023, h = o >> 6, d = o & 63;
                    *(__half2*)(dst + ((size_t)((b*NH + h)*SEQ + nn))*HD + d) =
                        __floats2half2_rn(v0, v1);
                } else {
                    float* p = Cout + (size_t)m * FEAT + o;
                    p[0] = v0 + bias[o]; p[1] = v1 + bias[o+1];
                }
            }
}

// =====================================================================
// passR: outv[row] = f( sum_col exp2(A_row . B_col) * wcol )
// wcol = 1/colw[col] if colw else 1;  out = 1/sum if recip else sum.
// passA: (q', k, null, g_r, 0) -> r_i ; passB: (k, q', g_r, g_w, 1) -> w_j
// Column weights preloaded once (fp16); exp via EX2.F16x2.
// =====================================================================
__global__ void __launch_bounds__(256) passR_kernel(
    const __half* __restrict__ Ag, const __half* __restrict__ Bg,
    const float* __restrict__ colw, float* __restrict__ outv, int recip)
{
    extern __shared__ __half sh[];
    __half (*Qs)[72] = (__half (*)[72])sh;                  // [128][72]
    __half* KsB = sh + 128*72;                              // [2][128][72]
    __half2* wh2 = (__half2*)(sh + 3*128*72);               // [512]
    float* red = (float*)(wh2 + 512);                       // [128][2]

    int bh = blockIdx.y, i0 = blockIdx.x * 128;
    int tid = threadIdx.x;
    int warp = tid >> 5, lane = tid & 31;
    int g = lane >> 2, t = lane & 3;
    int wm = (warp >> 1) * 32, wn = (warp & 1) * 64;
    const __half* Ab = Ag + (size_t)bh*SEQ*HD;
    const __half* Bb = Bg + (size_t)bh*SEQ*HD;

    {   // A tile once
        int lr = tid >> 1, lc = (tid & 1) * 32;
        const __half* src = Ab + (size_t)(i0 + lr)*HD + lc;
        *(uint4*)&Qs[lr][lc+0]  = *(const uint4*)(src+0);
        *(uint4*)&Qs[lr][lc+8]  = *(const uint4*)(src+8);
        *(uint4*)&Qs[lr][lc+16] = *(const uint4*)(src+16);
        *(uint4*)&Qs[lr][lc+24] = *(const uint4*)(src+24);
    }
    if (colw) {   // preload all 1024 column weights as fp16 reciprocals
        const float* cw = colw + (size_t)bh*SEQ;
#pragma unroll
        for (int q = 0; q < 2; q++) {
            int idx = tid + q*256;
            wh2[idx] = __floats2half2_rn(1.f / cw[2*idx], 1.f / cw[2*idx+1]);
        }
    }

    auto loadK = [&](int s, int j0) {
        __half* Ks = KsB + s * 128*72;
#pragma unroll
        for (int q = 0; q < 4; q++) {
            int c = tid*4 + q;
            int row = c >> 3, off = (c & 7) * 8;
            CPA16(sptr(Ks + row*72 + off), Bb + (size_t)(j0+row)*HD + off);
        }
    };
    loadK(0, 0);   CPCOMMIT();
    loadK(1, 128); CPCOMMIT();

    float rs[2][2] = {{0.f,0.f},{0.f,0.f}};

    for (int jt = 0; jt < 8; jt++) {
        int j0 = jt * 128, st = jt & 1;
        const __half* Ks = KsB + st * 128*72;
        CPWAIT(1); __syncthreads();

        float acc[2][8][4];
#pragma unroll
        for (int mi = 0; mi < 2; mi++)
#pragma unroll
            for (int ni = 0; ni < 8; ni++)
#pragma unroll
                for (int c = 0; c < 4; c++) acc[mi][ni][c] = 0.f;

#pragma unroll
        for (int kk = 0; kk < 64; kk += 16) {
            unsigned a[2][4], b[8][2];
#pragma unroll
            for (int mi = 0; mi < 2; mi++) {
                int r0 = wm + mi*16 + g;
                a[mi][0] = *(const unsigned*)(&Qs[r0  ][kk + 2*t]);
                a[mi][1] = *(const unsigned*)(&Qs[r0+8][kk + 2*t]);
                a[mi][2] = *(const unsigned*)(&Qs[r0  ][kk + 2*t + 8]);
                a[mi][3] = *(const unsigned*)(&Qs[r0+8][kk + 2*t + 8]);
            }
#pragma unroll
            for (int ni = 0; ni < 8; ni++) {
                int c0 = wn + ni*8 + g;
                b[ni][0] = *(const unsigned*)(Ks + c0*72 + kk + 2*t);
                b[ni][1] = *(const unsigned*)(Ks + c0*72 + kk + 2*t + 8);
            }
#pragma unroll
            for (int mi = 0; mi < 2; mi++)
#pragma unroll
                for (int ni = 0; ni < 8; ni++)
                    mma_f16(acc[mi][ni], a[mi], b[ni]);
        }
        __syncthreads();                  // all warps done with Ks[st]
        if (jt + 2 < 8) loadK(st, (jt+2)*128);
        CPCOMMIT();

        // epilogue (overlaps the async loads): exp2 in fp16x2
#pragma unroll
        for (int mi = 0; mi < 2; mi++)
#pragma unroll
            for (int ri = 0; ri < 2; ri++) {
                float sum = 0.f;
#pragma unroll
                for (int ni = 0; ni < 8; ni++) {
                    int c0 = wn + ni*8 + 2*t;
                    __half2 hx = h2exp2(__floats2half2_rn(
                        acc[mi][ni][ri*2+0], acc[mi][ni][ri*2+1]));
                    if (colw) hx = __hmul2(hx, wh2[(j0 + c0) >> 1]);
                    float2 f = __half22float2(hx);
                    sum += f.x + f.y;
                }
                rs[mi][ri] += sum;
            }
    }

#pragma unroll
    for (int mi = 0; mi < 2; mi++)
#pragma unroll
        for (int ri = 0; ri < 2; ri++) {
            float v = rs[mi][ri];
            v += __shfl_xor_sync(0xffffffffu, v, 1);
            v += __shfl_xor_sync(0xffffffffu, v, 2);
            if (t == 0) red[(wm + mi*16 + g + ri*8)*2 + (warp & 1)] = v;
        }
    __syncthreads();
    if (tid < 128) {
        float s = red[tid*2] + red[tid*2 + 1];
        outv[(size_t)bh*SEQ + i0 + tid] = recip ? (1.f / s) : s;
    }
}

// =====================================================================
// passC (flash-style): out_i = (1/n)(sum_j e^{dots} w_j v_j)/(sum_j e^{dots} w_j)
// K and V both in 2-stage cp.async pipeline; V^T B-fragments via
// ldmatrix.trans (no manual transpose); P built fp16 in registers.
// =====================================================================
#define CSTG (2*128*72)   // K + V per stage (halves)
__global__ void __launch_bounds__(256) passC_kernel()
{
    extern __shared__ __half sh[];
    __half (*Qs)[72] = (__half (*)[72])sh;                  // [128][72]
    __half* KVs = sh + 128*72;                              // [2][K|V]
    __half2* wh2 = (__half2*)(sh + 128*72 + 2*CSTG);        // [512]

    int bh = blockIdx.y;
    int b = bh / NH, h = bh % NH;
    int i0 = blockIdx.x * 128;
    int tid = threadIdx.x;
    int warp = tid >> 5, lane = tid & 31;
    int g = lane >> 2, t = lane & 3;
    int wm = warp * 16;

    const __half* Qb = g_qh + (size_t)bh*SEQ*HD;
    const __half* Kb = g_kh + (size_t)bh*SEQ*HD;
    const __half* Vb = g_vh + (size_t)bh*SEQ*HD;
    const float* wg = g_w + (size_t)bh*SEQ;

    {   // Q tile once
        int lr = tid >> 1, lc = (tid & 1) * 32;
        const __half* src = Qb + (size_t)(i0 + lr)*HD + lc;
        *(uint4*)&Qs[lr][lc+0]  = *(const uint4*)(src+0);
        *(uint4*)&Qs[lr][lc+8]  = *(const uint4*)(src+8);
        *(uint4*)&Qs[lr][lc+16] = *(const uint4*)(src+16);
        *(uint4*)&Qs[lr][lc+24] = *(const uint4*)(src+24);
    }
    {   // preload all 1024 w as fp16
#pragma unroll
        for (int q = 0; q < 2; q++) {
            int idx = tid + q*256;
            wh2[idx] = __floats2half2_rn(wg[2*idx], wg[2*idx+1]);
        }
    }

    auto loadKV = [&](int s, int j0) {
        __half* Ks = KVs + s * CSTG;
        __half* Vs = Ks + 128*72;
#pragma unroll
        for (int q = 0; q < 4; q++) {
            int c = tid*4 + q;
            int row = c >> 3, off = (c & 7) * 8;
            CPA16(sptr(Ks + row*72 + off), Kb + (size_t)(j0+row)*HD + off);
            CPA16(sptr(Vs + row*72 + off), Vb + (size_t)(j0+row)*HD + off);
        }
    };
    loadKV(0, 0);   CPCOMMIT();
    loadKV(1, 128); CPCOMMIT();

    float oacc[8][4];
#pragma unroll
    for (int nd = 0; nd < 8; nd++)
#pragma unroll
        for (int c = 0; c < 4; c++) oacc[nd][c] = 0.f;
    float den0 = 0.f, den1 = 0.f;

    for (int jt = 0; jt < 8; jt++) {
        int j0 = jt * 128, st = jt & 1;
        const __half* Ks = KVs + st * CSTG;
        const __half* Vs = Ks + 128*72;
        CPWAIT(1); __syncthreads();

        // S = Q K^T  (16 rows x 128 cols per warp)
        float sacc[16][4];
#pragma unroll
        for (int ni = 0; ni < 16; ni++)
#pragma unroll
            for (int c = 0; c < 4; c++) sacc[ni][c] = 0.f;

#pragma unroll
        for (int kk = 0; kk < 64; kk += 16) {
            unsigned a[4];
            a[0] = *(const unsigned*)(&Qs[wm + g    ][kk + 2*t]);
            a[1] = *(const unsigned*)(&Qs[wm + g + 8][kk + 2*t]);
            a[2] = *(const unsigned*)(&Qs[wm + g    ][kk + 2*t + 8]);
            a[3] = *(const unsigned*)(&Qs[wm + g + 8][kk + 2*t + 8]);
#pragma unroll
            for (int ni = 0; ni < 16; ni++) {
                unsigned bb[2];
                bb[0] = *(const unsigned*)(Ks + (ni*8 + g)*72 + kk + 2*t);
                bb[1] = *(const unsigned*)(Ks + (ni*8 + g)*72 + kk + 2*t + 8);
                mma_f16(sacc[ni], a, bb);
            }
        }

        // P = exp2(S)*w in fp16 registers (A fragments) + denominator
        unsigned aP[8][4];
#pragma unroll
        for (int ni = 0; ni < 16; ni++) {
            int c0 = ni*8 + 2*t;
            __half2 w2 = wh2[(j0 + c0) >> 1];
            __half2 hA = __hmul2(h2exp2(__floats2half2_rn(sacc[ni][0], sacc[ni][1])), w2);
            __half2 hB = __hmul2(h2exp2(__floats2half2_rn(sacc[ni][2], sacc[ni][3])), w2);
            float2 fa = __half22float2(hA), fb = __half22float2(hB);
            den0 += fa.x + fa.y; den1 += fb.x + fb.y;
            int kc = ni >> 1;
            if ((ni & 1) == 0) {
                aP[kc][0] = *(unsigned*)&hA; aP[kc][1] = *(unsigned*)&hB;
            } else {
                aP[kc][2] = *(unsigned*)&hA; aP[kc][3] = *(unsigned*)&hB;
            }
        }

        // O += P @ V^T  (B fragments via ldmatrix.trans on [j][d] tile)
        unsigned vbase = sptr(Vs + (lane & 15)*72);
#pragma unroll
        for (int kc = 0; kc < 8; kc++) {
            unsigned rowb = vbase + kc*16*144;   // 16 rows * 144 B/row
#pragma unroll
            for (int nd = 0; nd < 8; nd++) {
                unsigned b0, b1;
                ldsm_x2_t(b0, b1, rowb + nd*16);
                unsigned bb[2] = {b0, b1};
                mma_f16(oacc[nd], aP[kc], bb);
            }
        }
        __syncthreads();   // all warps done with Ks/Vs[st]
        if (jt + 2 < 8) loadKV(st, (jt+2)*128);
        CPCOMMIT();
    }

    // normalize + write ctx (fp16, [b, n, h*64+d])
    den0 += __shfl_xor_sync(0xffffffffu, den0, 1);
    den0 += __shfl_xor_sync(0xffffffffu, den0, 2);
    den1 += __shfl_xor_sync(0xffffffffu, den1, 1);
    den1 += __shfl_xor_sync(0xffffffffu, den1, 2);
    const float inv_n = 1.f / (float)SEQ;
    float is0 = inv_n / den0, is1 = inv_n / den1;

    int row0 = i0 + wm + g, row1 = row0 + 8;
#pragma unroll
    for (int nd = 0; nd < 8; nd++) {
        int col = h*HD + nd*8 + 2*t;
        *(__half2*)(g_ctxh + ((size_t)(b*SEQ + row0))*FEAT + col) =
            __floats2half2_rn(oacc[nd][0]*is0, oacc[nd][1]*is0);
        *(__half2*)(g_ctxh + ((size_t)(b*SEQ + row1))*FEAT + col) =
            __floats2half2_rn(oacc[nd][2]*is1, oacc[nd][3]*is1);
    }
}

// =====================================================================
extern "C" void kernel_launch(void* const* d_in, const int* in_sizes, int n_in,
                              void* d_out, int out_size)
{
    const float* x  = (const float*)d_in[0];
    const float* Wq = (const float*)d_in[1];
    const float* Wk = (const float*)d_in[2];
    const float* Wv = (const float*)d_in[3];
    const float* Wo = (const float*)d_in[4];
    const float* bo = (const float*)d_in[5];
    float* out = (float*)d_out;

    const int gemm_smem  = 6 * GSTG * 2;                          // 61440
    const int passR_smem = 3*128*72*2 + 512*4 + 256*4;            // 58368
    const int passC_smem = (128*72 + 2*CSTG)*2 + 512*4;           // 94208
    cudaFuncSetAttribute(gemm_h_kernel, cudaFuncAttributeMaxDynamicSharedMemorySize, gemm_smem);
    cudaFuncSetAttribute(passR_kernel,  cudaFuncAttributeMaxDynamicSharedMemorySize, passR_smem);
    cudaFuncSetAttribute(passC_kernel,  cudaFuncAttributeMaxDynamicSharedMemorySize, passC_smem);

    __half *xh, *wh, *ctxh, *qp, *kp;
    float *rp, *wp;
    cudaGetSymbolAddress((void**)&xh,   g_xh);
    cudaGetSymbolAddress((void**)&wh,   g_wh);
    cudaGetSymbolAddress((void**)&ctxh, g_ctxh);
    cudaGetSymbolAddress((void**)&qp,   g_qh);
    cudaGetSymbolAddress((void**)&kp,   g_kh);
    cudaGetSymbolAddress((void**)&rp,   g_r);
    cudaGetSymbolAddress((void**)&wp,   g_w);

    // 0) fp32 -> fp16 copies
    {
        int nx4 = Bsz*SEQ*FEAT/4;
        int nw4 = FEAT*FEAT/4;
        cvt_kernel<<<(nx4+255)/256, 256>>>((const float4*)x, (__half2*)xh, nx4);
        cvtW_kernel<<<dim3((nw4+255)/256, 4), 256>>>(
            (const float4*)Wq, (const float4*)Wk, (const float4*)Wv, (const float4*)Wo,
            (__half2*)wh, nw4);
    }

    // 1) QKV projection -> fp16 q'(pre-scaled)/k/v
    gemm_h_kernel<<<dim3(FEAT/128, (Bsz*SEQ)/128, 3), 256, gemm_smem>>>(
        xh, wh, nullptr, nullptr, 0);

    dim3 ag(SEQ/128, BHN);
    // 2) r_i = sum_j e^{dots_ij}
    passR_kernel<<<ag, 256, passR_smem>>>(qp, kp, nullptr, rp, 0);
    // 3) w_j = 1 / sum_i e^{dots_ij} / r_i
    passR_kernel<<<ag, 256, passR_smem>>>(kp, qp, rp, wp, 1);
    // 4) ctx (flash-style, register P, ldmatrix.trans V)
    passC_kernel<<<ag, 256, passC_smem>>>();
    // 5) out = ctx @ Wo^T + bo
    gemm_h_kernel<<<dim3(FEAT/128, (Bsz*SEQ)/128, 1), 256, gemm_smem>>>(
        ctxh, wh + (size_t)3*FEAT*FEAT, bo, out, 1);
}

// round 7
// speedup vs baseline: 10.1772x; 1.0099x over previous
#include <cuda_runtime.h>
#include <cuda_fp16.h>
#include <math.h>

#define Bsz  8
#define SEQ  1024
#define FEAT 768
#define NH   12
#define HD   64
#define BHN  (Bsz*NH)            // 96
#define LOG2E 1.4426950408889634f
#define QSCL 0.1803368801111204f // 0.125 * log2(e)

// ---------------- static device scratch (no cudaMalloc) ----------------
__device__ __half g_qh[BHN*SEQ*HD];           // pre-scaled by QSCL
__device__ __half g_kh[BHN*SEQ*HD];
__device__ __half g_vh[BHN*SEQ*HD];
__device__ __half g_xh[Bsz*SEQ*FEAT];
__device__ __half g_wh[4*FEAT*FEAT];          // Wq,Wk,Wv,Wo fp16
__device__ __half g_ctxh[Bsz*SEQ*FEAT];
__device__ float  g_r[BHN*SEQ];               // r_i = sum_j e^{dots_ij}
__device__ float  g_w[BHN*SEQ];               // w_j = e^{v1_j}

// ---------------- helpers ----------------
__device__ __forceinline__ unsigned sptr(const void* p) {
    unsigned r;
    asm("{ .reg .u64 t; cvta.to.shared.u64 t, %1; cvt.u32.u64 %0, t; }"
        : "=r"(r) : "l"(p));
    return r;
}
#define CPA16(dst, src) \
    asm volatile("cp.async.ca.shared.global [%0], [%1], 16;\n" :: "r"(dst), "l"(src))
#define CPCOMMIT() asm volatile("cp.async.commit_group;\n")
#define CPWAIT(n)  asm volatile("cp.async.wait_group %0;\n" :: "n"(n))

__device__ __forceinline__ void mma_f16(float* c, const unsigned* a, const unsigned* b) {
    asm volatile(
        "mma.sync.aligned.m16n8k16.row.col.f32.f16.f16.f32 "
        "{%0,%1,%2,%3}, {%4,%5,%6,%7}, {%8,%9}, {%0,%1,%2,%3};\n"
        : "+f"(c[0]), "+f"(c[1]), "+f"(c[2]), "+f"(c[3])
        : "r"(a[0]), "r"(a[1]), "r"(a[2]), "r"(a[3]), "r"(b[0]), "r"(b[1]));
}

__device__ __forceinline__ void ldsm_x2_t(unsigned& r0, unsigned& r1, unsigned addr) {
    asm volatile("ldmatrix.sync.aligned.m8n8.x2.trans.shared.b16 {%0,%1}, [%2];\n"
        : "=r"(r0), "=r"(r1) : "r"(addr));
}

// =====================================================================
// fp32 -> fp16 converts
// =====================================================================
__global__ void cvt_kernel(const float4* __restrict__ s, __half2* __restrict__ d, int n4)
{
    int i = blockIdx.x * 256 + threadIdx.x;
    if (i < n4) {
        float4 v = s[i];
        d[2*i+0] = __floats2half2_rn(v.x, v.y);
        d[2*i+1] = __floats2half2_rn(v.z, v.w);
    }
}

__global__ void cvtW_kernel(const float4* __restrict__ s0, const float4* __restrict__ s1,
                            const float4* __restrict__ s2, const float4* __restrict__ s3,
                            __half2* __restrict__ d, int n4)
{
    const float4* s = (blockIdx.y == 0) ? s0 : (blockIdx.y == 1) ? s1
                    : (blockIdx.y == 2) ? s2 : s3;
    __half2* dd = d + (size_t)blockIdx.y * n4 * 2;
    int i = blockIdx.x * 256 + threadIdx.x;
    if (i < n4) {
        float4 v = s[i];
        dd[2*i+0] = __floats2half2_rn(v.x, v.y);
        dd[2*i+1] = __floats2half2_rn(v.z, v.w);
    }
}

// =====================================================================
// Pipelined fp16 tensor-core GEMM (NT): C[m,o] = sum_f A[m,f]*W[o,f].
// 3-stage cp.async, 128x128 tile, BK=32, 8 warps (4m x 2n), 2 CTAs/SM.
// =====================================================================
#define GSTG (128*40)
__global__ void __launch_bounds__(256, 2) gemm_h_kernel(
    const __half* __restrict__ A, const __half* __restrict__ Wbase,
    const float* __restrict__ bias, float* __restrict__ Cout, int mode)
{
    extern __shared__ __half gsm[];   // As[3][128][40] | Bs[3][128][40]

    const __half* W = Wbase + (size_t)blockIdx.z * FEAT * FEAT;
    int tid = threadIdx.x;
    int m0 = blockIdx.y * 128, n0 = blockIdx.x * 128;
    int warp = tid >> 5, lane = tid & 31;
    int wm = (warp >> 1) * 32, wn = (warp & 1) * 64;
    int g = lane >> 2, t = lane & 3;

    auto load_stage = [&](int s, int k0) {
        __half* As = gsm + s * GSTG;
        __half* Bs = gsm + 3*GSTG + s * GSTG;
#pragma unroll
        for (int q = 0; q < 2; q++) {
            int c = tid*2 + q;
            int row = c >> 2, off = (c & 3) * 8;
            CPA16(sptr(As + row*40 + off), A + (size_t)(m0+row)*FEAT + k0 + off);
            CPA16(sptr(Bs + row*40 + off), W + (size_t)(n0+row)*FEAT + k0 + off);
        }
    };

#pragma unroll
    for (int s = 0; s < 3; s++) { load_stage(s, s*32); CPCOMMIT(); }

    float acc[2][8][4];
#pragma unroll
    for (int mi = 0; mi < 2; mi++)
#pragma unroll
        for (int ni = 0; ni < 8; ni++)
#pragma unroll
            for (int c = 0; c < 4; c++) acc[mi][ni][c] = 0.f;

    const int NT = FEAT / 32;   // 24
    for (int kt = 0; kt < NT; kt++) {
        CPWAIT(2); __syncthreads();
        int st = kt % 3;
        const __half* As = gsm + st * GSTG;
        const __half* Bs = gsm + 3*GSTG + st * GSTG;
#pragma unroll
        for (int kk = 0; kk < 32; kk += 16) {
            unsigned a[2][4], b[8][2];
#pragma unroll
            for (int mi = 0; mi < 2; mi++) {
                int r0 = wm + mi*16 + g;
                a[mi][0] = *(const unsigned*)(As + (r0  )*40 + kk + 2*t);
                a[mi][1] = *(const unsigned*)(As + (r0+8)*40 + kk + 2*t);
                a[mi][2] = *(const unsigned*)(As + (r0  )*40 + kk + 2*t + 8);
                a[mi][3] = *(const unsigned*)(As + (r0+8)*40 + kk + 2*t + 8);
            }
#pragma unroll
            for (int ni = 0; ni < 8; ni++) {
                int c0 = wn + ni*8 + g;
                b[ni][0] = *(const unsigned*)(Bs + c0*40 + kk + 2*t);
                b[ni][1] = *(const unsigned*)(Bs + c0*40 + kk + 2*t + 8);
            }
#pragma unroll
            for (int mi = 0; mi < 2; mi++)
#pragma unroll
                for (int ni = 0; ni < 8; ni++)
                    mma_f16(acc[mi][ni], a[mi], b[ni]);
        }
        __syncthreads();
        if (kt + 3 < NT) load_stage(st, (kt+3)*32);
        CPCOMMIT();
    }

    float scl = (mode == 0 && blockIdx.z == 0) ? QSCL : 1.f;
#pragma unroll
    for (int mi = 0; mi < 2; mi++)
#pragma unroll
        for (int ni = 0; ni < 8; ni++)
#pragma unroll
            for (int ri = 0; ri < 2; ri++) {
                int m = m0 + wm + mi*16 + g + ri*8;
                int o = n0 + wn + ni*8 + 2*t;
                float v0 = acc[mi][ni][ri*2+0] * scl;
                float v1 = acc[mi][ni][ri*2+1] * scl;
                if (mode == 0) {
                    __half* dst = (blockIdx.z == 0) ? g_qh : (blockIdx.z == 1) ? g_kh : g_vh;
                    int b = m >> 10, nn = m & 1023, h = o >> 6, d = o & 63;
                    *(__half2*)(dst + ((size_t)((b*NH + h)*SEQ + nn))*HD + d) =
                        __floats2half2_rn(v0, v1);
                } else {
                    float* p = Cout + (size_t)m * FEAT + o;
                    p[0] = v0 + bias[o]; p[1] = v1 + bias[o+1];
                }
            }
}

// =====================================================================
// passR: outv[row] = f( sum_col exp2(A_row . B_col) * wcol ), 2 CTAs/SM.
// passA: (q', k, null, g_r, 0) -> r_i ; passB: (k, q', g_r, g_w, 1) -> w_j
// =====================================================================
__global__ void __launch_bounds__(256, 2) passR_kernel(
    const __half* __restrict__ Ag, const __half* __restrict__ Bg,
    const float* __restrict__ colw, float* __restrict__ outv, int recip)
{
    extern __shared__ __half sh[];
    __half (*Qs)[72] = (__half (*)[72])sh;                  // [128][72]
    __half* KsB = sh + 128*72;                              // [2][128][72]
    __half2* wh2 = (__half2*)(sh + 3*128*72);               // [512]
    float* red = (float*)(wh2 + 512);                       // [128][2]

    int bh = blockIdx.y, i0 = blockIdx.x * 128;
    int tid = threadIdx.x;
    int warp = tid >> 5, lane = tid & 31;
    int g = lane >> 2, t = lane & 3;
    int wm = (warp >> 1) * 32, wn = (warp & 1) * 64;
    const __half* Ab = Ag + (size_t)bh*SEQ*HD;
    const __half* Bb = Bg + (size_t)bh*SEQ*HD;

    {   // A tile once
        int lr = tid >> 1, lc = (tid & 1) * 32;
        const __half* src = Ab + (size_t)(i0 + lr)*HD + lc;
        *(uint4*)&Qs[lr][lc+0]  = *(const uint4*)(src+0);
        *(uint4*)&Qs[lr][lc+8]  = *(const uint4*)(src+8);
        *(uint4*)&Qs[lr][lc+16] = *(const uint4*)(src+16);
        *(uint4*)&Qs[lr][lc+24] = *(const uint4*)(src+24);
    }
    if (colw) {   // preload all 1024 column weights as fp16 reciprocals
        const float* cw = colw + (size_t)bh*SEQ;
#pragma unroll
        for (int q = 0; q < 2; q++) {
            int idx = tid + q*256;
            wh2[idx] = __floats2half2_rn(1.f / cw[2*idx], 1.f / cw[2*idx+1]);
        }
    }

    auto loadK = [&](int s, int j0) {
        __half* Ks = KsB + s * 128*72;
#pragma unroll
        for (int q = 0; q < 4; q++) {
            int c = tid*4 + q;
            int row = c >> 3, off = (c & 7) * 8;
            CPA16(sptr(Ks + row*72 + off), Bb + (size_t)(j0+row)*HD + off);
        }
    };
    loadK(0, 0);   CPCOMMIT();
    loadK(1, 128); CPCOMMIT();

    float rs[2][2] = {{0.f,0.f},{0.f,0.f}};

    for (int jt = 0; jt < 8; jt++) {
        int j0 = jt * 128, st = jt & 1;
        const __half* Ks = KsB + st * 128*72;
        CPWAIT(1); __syncthreads();

        float acc[2][8][4];
#pragma unroll
        for (int mi = 0; mi < 2; mi++)
#pragma unroll
            for (int ni = 0; ni < 8; ni++)
#pragma unroll
                for (int c = 0; c < 4; c++) acc[mi][ni][c] = 0.f;

#pragma unroll
        for (int kk = 0; kk < 64; kk += 16) {
            unsigned a[2][4], b[8][2];
#pragma unroll
            for (int mi = 0; mi < 2; mi++) {
                int r0 = wm + mi*16 + g;
                a[mi][0] = *(const unsigned*)(&Qs[r0  ][kk + 2*t]);
                a[mi][1] = *(const unsigned*)(&Qs[r0+8][kk + 2*t]);
                a[mi][2] = *(const unsigned*)(&Qs[r0  ][kk + 2*t + 8]);
                a[mi][3] = *(const unsigned*)(&Qs[r0+8][kk + 2*t + 8]);
            }
#pragma unroll
            for (int ni = 0; ni < 8; ni++) {
                int c0 = wn + ni*8 + g;
                b[ni][0] = *(const unsigned*)(Ks + c0*72 + kk + 2*t);
                b[ni][1] = *(const unsigned*)(Ks + c0*72 + kk + 2*t + 8);
            }
#pragma unroll
            for (int mi = 0; mi < 2; mi++)
#pragma unroll
                for (int ni = 0; ni < 8; ni++)
                    mma_f16(acc[mi][ni], a[mi], b[ni]);
        }
        __syncthreads();                  // all warps done with Ks[st]
        if (jt + 2 < 8) loadK(st, (jt+2)*128);
        CPCOMMIT();

        // epilogue (overlaps the async loads): exp2 in fp16x2
#pragma unroll
        for (int mi = 0; mi < 2; mi++)
#pragma unroll
            for (int ri = 0; ri < 2; ri++) {
                float sum = 0.f;
#pragma unroll
                for (int ni = 0; ni < 8; ni++) {
                    int c0 = wn + ni*8 + 2*t;
                    __half2 hx = h2exp2(__floats2half2_rn(
                        acc[mi][ni][ri*2+0], acc[mi][ni][ri*2+1]));
                    if (colw) hx = __hmul2(hx, wh2[(j0 + c0) >> 1]);
                    float2 f = __half22float2(hx);
                    sum += f.x + f.y;
                }
                rs[mi][ri] += sum;
            }
    }

#pragma unroll
    for (int mi = 0; mi < 2; mi++)
#pragma unroll
        for (int ri = 0; ri < 2; ri++) {
            float v = rs[mi][ri];
            v += __shfl_xor_sync(0xffffffffu, v, 1);
            v += __shfl_xor_sync(0xffffffffu, v, 2);
            if (t == 0) red[(wm + mi*16 + g + ri*8)*2 + (warp & 1)] = v;
        }
    __syncthreads();
    if (tid < 128) {
        float s = red[tid*2] + red[tid*2 + 1];
        outv[(size_t)bh*SEQ + i0 + tid] = recip ? (1.f / s) : s;
    }
}

// =====================================================================
// passC (flash-style): out_i = (1/n)(sum_j e^{dots} w_j v_j)/(sum_j e^{dots} w_j)
// j-tile processed in two 64-col halves to fit 2 CTAs/SM (smaller live set).
// =====================================================================
#define CSTG (2*128*72)   // K + V per stage
__global__ void __launch_bounds__(256, 2) passC_kernel()
{
    extern __shared__ __half sh[];
    __half (*Qs)[72] = (__half (*)[72])sh;                  // [128][72]
    __half* KVs = sh + 128*72;                              // [2][K|V]
    __half2* wh2 = (__half2*)(sh + 128*72 + 2*CSTG);        // [512]

    int bh = blockIdx.y;
    int b = bh / NH, h = bh % NH;
    int i0 = blockIdx.x * 128;
    int tid = threadIdx.x;
    int warp = tid >> 5, lane = tid & 31;
    int g = lane >> 2, t = lane & 3;
    int wm = warp * 16;

    const __half* Qb = g_qh + (size_t)bh*SEQ*HD;
    const __half* Kb = g_kh + (size_t)bh*SEQ*HD;
    const __half* Vb = g_vh + (size_t)bh*SEQ*HD;
    const float* wg = g_w + (size_t)bh*SEQ;

    {   // Q tile once
        int lr = tid >> 1, lc = (tid & 1) * 32;
        const __half* src = Qb + (size_t)(i0 + lr)*HD + lc;
        *(uint4*)&Qs[lr][lc+0]  = *(const uint4*)(src+0);
        *(uint4*)&Qs[lr][lc+8]  = *(const uint4*)(src+8);
        *(uint4*)&Qs[lr][lc+16] = *(const uint4*)(src+16);
        *(uint4*)&Qs[lr][lc+24] = *(const uint4*)(src+24);
    }
    {   // preload all 1024 w as fp16
#pragma unroll
        for (int q = 0; q < 2; q++) {
            int idx = tid + q*256;
            wh2[idx] = __floats2half2_rn(wg[2*idx], wg[2*idx+1]);
        }
    }

    auto loadKV = [&](int s, int j0) {
        __half* Ks = KVs + s * CSTG;
        __half* Vs = Ks + 128*72;
#pragma unroll
        for (int q = 0; q < 4; q++) {
            int c = tid*4 + q;
            int row = c >> 3, off = (c & 7) * 8;
            CPA16(sptr(Ks + row*72 + off), Kb + (size_t)(j0+row)*HD + off);
            CPA16(sptr(Vs + row*72 + off), Vb + (size_t)(j0+row)*HD + off);
        }
    };
    loadKV(0, 0);   CPCOMMIT();
    loadKV(1, 128); CPCOMMIT();

    float oacc[8][4];
#pragma unroll
    for (int nd = 0; nd < 8; nd++)
#pragma unroll
        for (int c = 0; c < 4; c++) oacc[nd][c] = 0.f;
    float den0 = 0.f, den1 = 0.f;

    for (int jt = 0; jt < 8; jt++) {
        int j0 = jt * 128, st = jt & 1;
        const __half* Ks = KVs + st * CSTG;
        const __half* Vs = Ks + 128*72;
        CPWAIT(1); __syncthreads();

#pragma unroll
        for (int half = 0; half < 2; half++) {
            const __half* Ksh = Ks + (half*64)*72;

            // S = Q K^T  (16 rows x 64 cols per warp)
            float sacc[8][4];
#pragma unroll
            for (int ni = 0; ni < 8; ni++)
#pragma unroll
                for (int c = 0; c < 4; c++) sacc[ni][c] = 0.f;

#pragma unroll
            for (int kk = 0; kk < 64; kk += 16) {
                unsigned a[4];
                a[0] = *(const unsigned*)(&Qs[wm + g    ][kk + 2*t]);
                a[1] = *(const unsigned*)(&Qs[wm + g + 8][kk + 2*t]);
                a[2] = *(const unsigned*)(&Qs[wm + g    ][kk + 2*t + 8]);
                a[3] = *(const unsigned*)(&Qs[wm + g + 8][kk + 2*t + 8]);
#pragma unroll
                for (int ni = 0; ni < 8; ni++) {
                    unsigned bb[2];
                    bb[0] = *(const unsigned*)(Ksh + (ni*8 + g)*72 + kk + 2*t);
                    bb[1] = *(const unsigned*)(Ksh + (ni*8 + g)*72 + kk + 2*t + 8);
                    mma_f16(sacc[ni], a, bb);
                }
            }

            // P = exp2(S)*w in fp16 registers (A fragments) + denominator
            unsigned aP[4][4];
#pragma unroll
            for (int ni = 0; ni < 8; ni++) {
                int c0 = half*64 + ni*8 + 2*t;
                __half2 w2 = wh2[(j0 + c0) >> 1];
                __half2 hA = __hmul2(h2exp2(__floats2half2_rn(sacc[ni][0], sacc[ni][1])), w2);
                __half2 hB = __hmul2(h2exp2(__floats2half2_rn(sacc[ni][2], sacc[ni][3])), w2);
                float2 fa = __half22float2(hA), fb = __half22float2(hB);
                den0 += fa.x + fa.y; den1 += fb.x + fb.y;
                int kc = ni >> 1;
                if ((ni & 1) == 0) {
                    aP[kc][0] = *(unsigned*)&hA; aP[kc][1] = *(unsigned*)&hB;
                } else {
                    aP[kc][2] = *(unsigned*)&hA; aP[kc][3] = *(unsigned*)&hB;
                }
            }

            // O += P @ V^T  (B fragments via ldmatrix.trans on [j][d] tile)
            unsigned vbase = sptr(Vs + (half*64 + (lane & 15))*72);
#pragma unroll
            for (int kc = 0; kc < 4; kc++) {
                unsigned rowb = vbase + kc*16*144;   // 16 rows * 144 B/row
#pragma unroll
                for (int nd = 0; nd < 8; nd++) {
                    unsigned b0, b1;
                    ldsm_x2_t(b0, b1, rowb + nd*16);
                    unsigned bb[2] = {b0, b1};
                    mma_f16(oacc[nd], aP[kc], bb);
                }
            }
        }
        __syncthreads();   // all warps done with Ks/Vs[st]
        if (jt + 2 < 8) loadKV(st, (jt+2)*128);
        CPCOMMIT();
    }

    // normalize + write ctx (fp16, [b, n, h*64+d])
    den0 += __shfl_xor_sync(0xffffffffu, den0, 1);
    den0 += __shfl_xor_sync(0xffffffffu, den0, 2);
    den1 += __shfl_xor_sync(0xffffffffu, den1, 1);
    den1 += __shfl_xor_sync(0xffffffffu, den1, 2);
    const float inv_n = 1.f / (float)SEQ;
    float is0 = inv_n / den0, is1 = inv_n / den1;

    int row0 = i0 + wm + g, row1 = row0 + 8;
#pragma unroll
    for (int nd = 0; nd < 8; nd++) {
        int col = h*HD + nd*8 + 2*t;
        *(__half2*)(g_ctxh + ((size_t)(b*SEQ + row0))*FEAT + col) =
            __floats2half2_rn(oacc[nd][0]*is0, oacc[nd][1]*is0);
        *(__half2*)(g_ctxh + ((size_t)(b*SEQ + row1))*FEAT + col) =
            __floats2half2_rn(oacc[nd][2]*is1, oacc[nd][3]*is1);
    }
}

// =====================================================================
extern "C" void kernel_launch(void* const* d_in, const int* in_sizes, int n_in,
                              void* d_out, int out_size)
{
    const float* x  = (const float*)d_in[0];
    const float* Wq = (const float*)d_in[1];
    const float* Wk = (const float*)d_in[2];
    const float* Wv = (const float*)d_in[3];
    const float* Wo = (const float*)d_in[4];
    const float* bo = (const float*)d_in[5];
    float* out = (float*)d_out;

    const int gemm_smem  = 6 * GSTG * 2;                          // 61440
    const int passR_smem = 3*128*72*2 + 512*4 + 256*4;            // 58368
    const int passC_smem = (128*72 + 2*CSTG)*2 + 512*4;           // 94208
    cudaFuncSetAttribute(gemm_h_kernel, cudaFuncAttributeMaxDynamicSharedMemorySize, gemm_smem);
    cudaFuncSetAttribute(passR_kernel,  cudaFuncAttributeMaxDynamicSharedMemorySize, passR_smem);
    cudaFuncSetAttribute(passC_kernel,  cudaFuncAttributeMaxDynamicSharedMemorySize, passC_smem);

    __half *xh, *wh, *ctxh, *qp, *kp;
    float *rp, *wp;
    cudaGetSymbolAddress((void**)&xh,   g_xh);
    cudaGetSymbolAddress((void**)&wh,   g_wh);
    cudaGetSymbolAddress((void**)&ctxh, g_ctxh);
    cudaGetSymbolAddress((void**)&qp,   g_qh);
    cudaGetSymbolAddress((void**)&kp,   g_kh);
    cudaGetSymbolAddress((void**)&rp,   g_r);
    cudaGetSymbolAddress((void**)&wp,   g_w);

    // 0) fp32 -> fp16 copies
    {
        int nx4 = Bsz*SEQ*FEAT/4;
        int nw4 = FEAT*FEAT/4;
        cvt_kernel<<<(nx4+255)/256, 256>>>((const float4*)x, (__half2*)xh, nx4);
        cvtW_kernel<<<dim3((nw4+255)/256, 4), 256>>>(
            (const float4*)Wq, (const float4*)Wk, (const float4*)Wv, (const float4*)Wo,
            (__half2*)wh, nw4);
    }

    // 1) QKV projection -> fp16 q'(pre-scaled)/k/v
    gemm_h_kernel<<<dim3(FEAT/128, (Bsz*SEQ)/128, 3), 256, gemm_smem>>>(
        xh, wh, nullptr, nullptr, 0);

    dim3 ag(SEQ/128, BHN);
    // 2) r_i = sum_j e^{dots_ij}
    passR_kernel<<<ag, 256, passR_smem>>>(qp, kp, nullptr, rp, 0);
    // 3) w_j = 1 / sum_i e^{dots_ij} / r_i
    passR_kernel<<<ag, 256, passR_smem>>>(kp, qp, rp, wp, 1);
    // 4) ctx (flash-style, register P, ldmatrix.trans V)
    passC_kernel<<<ag, 256, passC_smem>>>();
    // 5) out = ctx @ Wo^T + bo
    gemm_h_kernel<<<dim3(FEAT/128, (Bsz*SEQ)/128, 1), 256, gemm_smem>>>(
        ctxh, wh + (size_t)3*FEAT*FEAT, bo, out, 1);
}

// round 8
// speedup vs baseline: 11.2601x; 1.1064x over previous
#include <cuda_runtime.h>
#include <cuda_fp16.h>
#include <math.h>

#define Bsz  8
#define SEQ  1024
#define FEAT 768
#define NH   12
#define HD   64
#define BHN  (Bsz*NH)            // 96
#define LOG2E 1.4426950408889634f
#define QSCL 0.1803368801111204f // 0.125 * log2(e)

// ---------------- static device scratch (no cudaMalloc) ----------------
__device__ __half g_qh[BHN*SEQ*HD];           // pre-scaled by QSCL
__device__ __half g_kh[BHN*SEQ*HD];
__device__ __half g_vh[BHN*SEQ*HD];
__device__ __half g_xh[Bsz*SEQ*FEAT];
__device__ __half g_wh[4*FEAT*FEAT];          // Wq,Wk,Wv,Wo fp16
__device__ __half g_ctxh[Bsz*SEQ*FEAT];
__device__ float  g_r[BHN*SEQ];               // r_i = sum_j e^{dots_ij}
__device__ float  g_w[BHN*SEQ];               // w_j = e^{v1_j}

// ---------------- helpers ----------------
__device__ __forceinline__ unsigned sptr(const void* p) {
    unsigned r;
    asm("{ .reg .u64 t; cvta.to.shared.u64 t, %1; cvt.u32.u64 %0, t; }"
        : "=r"(r) : "l"(p));
    return r;
}
#define CPA16(dst, src) \
    asm volatile("cp.async.ca.shared.global [%0], [%1], 16;\n" :: "r"(dst), "l"(src))
#define CPCOMMIT() asm volatile("cp.async.commit_group;\n")
#define CPWAIT(n)  asm volatile("cp.async.wait_group %0;\n" :: "n"(n))

__device__ __forceinline__ void mma_f16(float* c, const unsigned* a, const unsigned* b) {
    asm volatile(
        "mma.sync.aligned.m16n8k16.row.col.f32.f16.f16.f32 "
        "{%0,%1,%2,%3}, {%4,%5,%6,%7}, {%8,%9}, {%0,%1,%2,%3};\n"
        : "+f"(c[0]), "+f"(c[1]), "+f"(c[2]), "+f"(c[3])
        : "r"(a[0]), "r"(a[1]), "r"(a[2]), "r"(a[3]), "r"(b[0]), "r"(b[1]));
}

__device__ __forceinline__ void ldsm_x4(unsigned& r0, unsigned& r1, unsigned& r2,
                                        unsigned& r3, unsigned addr) {
    asm volatile("ldmatrix.sync.aligned.m8n8.x4.shared.b16 {%0,%1,%2,%3}, [%4];\n"
        : "=r"(r0), "=r"(r1), "=r"(r2), "=r"(r3) : "r"(addr));
}
__device__ __forceinline__ void ldsm_x2_t(unsigned& r0, unsigned& r1, unsigned addr) {
    asm volatile("ldmatrix.sync.aligned.m8n8.x2.trans.shared.b16 {%0,%1}, [%2];\n"
        : "=r"(r0), "=r"(r1) : "r"(addr));
}

// =====================================================================
// fp32 -> fp16 converts
// =====================================================================
__global__ void cvt_kernel(const float4* __restrict__ s, __half2* __restrict__ d, int n4)
{
    int i = blockIdx.x * 256 + threadIdx.x;
    if (i < n4) {
        float4 v = s[i];
        d[2*i+0] = __floats2half2_rn(v.x, v.y);
        d[2*i+1] = __floats2half2_rn(v.z, v.w);
    }
}

__global__ void cvtW_kernel(const float4* __restrict__ s0, const float4* __restrict__ s1,
                            const float4* __restrict__ s2, const float4* __restrict__ s3,
                            __half2* __restrict__ d, int n4)
{
    const float4* s = (blockIdx.y == 0) ? s0 : (blockIdx.y == 1) ? s1
                    : (blockIdx.y == 2) ? s2 : s3;
    __half2* dd = d + (size_t)blockIdx.y * n4 * 2;
    int i = blockIdx.x * 256 + threadIdx.x;
    if (i < n4) {
        float4 v = s[i];
        dd[2*i+0] = __floats2half2_rn(v.x, v.y);
        dd[2*i+1] = __floats2half2_rn(v.z, v.w);
    }
}

// =====================================================================
// Pipelined fp16 tensor-core GEMM (NT), ldmatrix fragment feeds.
// 3-stage cp.async, 128x128 tile, BK=32, 8 warps (4m x 2n).
// =====================================================================
#define GSTG (128*40)
__global__ void __launch_bounds__(256, 2) gemm_h_kernel(
    const __half* __restrict__ A, const __half* __restrict__ Wbase,
    const float* __restrict__ bias, float* __restrict__ Cout, int mode)
{
    extern __shared__ __half gsm[];   // As[3][128][40] | Bs[3][128][40]

    const __half* W = Wbase + (size_t)blockIdx.z * FEAT * FEAT;
    int tid = threadIdx.x;
    int m0 = blockIdx.y * 128, n0 = blockIdx.x * 128;
    int warp = tid >> 5, lane = tid & 31;
    int wm = (warp >> 1) * 32, wn = (warp & 1) * 64;
    int g = lane >> 2, t = lane & 3;

    // ldmatrix address components
    int arow = (lane & 15), acol8 = (lane >> 4) * 8;                    // A x4
    int brow = (lane & 7) + ((lane >> 4) & 1) * 8, bcol8 = ((lane >> 3) & 1) * 8; // B x4 pair

    auto load_stage = [&](int s, int k0) {
        __half* As = gsm + s * GSTG;
        __half* Bs = gsm + 3*GSTG + s * GSTG;
#pragma unroll
        for (int q = 0; q < 2; q++) {
            int c = tid*2 + q;
            int row = c >> 2, off = (c & 3) * 8;
            CPA16(sptr(As + row*40 + off), A + (size_t)(m0+row)*FEAT + k0 + off);
            CPA16(sptr(Bs + row*40 + off), W + (size_t)(n0+row)*FEAT + k0 + off);
        }
    };

#pragma unroll
    for (int s = 0; s < 3; s++) { load_stage(s, s*32); CPCOMMIT(); }

    float acc[2][8][4];
#pragma unroll
    for (int mi = 0; mi < 2; mi++)
#pragma unroll
        for (int ni = 0; ni < 8; ni++)
#pragma unroll
            for (int c = 0; c < 4; c++) acc[mi][ni][c] = 0.f;

    const int NT = FEAT / 32;   // 24
    for (int kt = 0; kt < NT; kt++) {
        CPWAIT(2); __syncthreads();
        int st = kt % 3;
        const __half* As = gsm + st * GSTG;
        const __half* Bs = gsm + 3*GSTG + st * GSTG;
#pragma unroll
        for (int kk = 0; kk < 32; kk += 16) {
            unsigned a[2][4];
#pragma unroll
            for (int mi = 0; mi < 2; mi++)
                ldsm_x4(a[mi][0], a[mi][1], a[mi][2], a[mi][3],
                        sptr(As + (wm + mi*16 + arow)*40 + kk + acol8));
#pragma unroll
            for (int np = 0; np < 4; np++) {
                unsigned b0, b1, b2, b3;
                ldsm_x4(b0, b1, b2, b3,
                        sptr(Bs + (wn + np*16 + brow)*40 + kk + bcol8));
                unsigned bb0[2] = {b0, b1}, bb1[2] = {b2, b3};
#pragma unroll
                for (int mi = 0; mi < 2; mi++) {
                    mma_f16(acc[mi][np*2+0], a[mi], bb0);
                    mma_f16(acc[mi][np*2+1], a[mi], bb1);
                }
            }
        }
        __syncthreads();
        if (kt + 3 < NT) load_stage(st, (kt+3)*32);
        CPCOMMIT();
    }

    float scl = (mode == 0 && blockIdx.z == 0) ? QSCL : 1.f;
#pragma unroll
    for (int mi = 0; mi < 2; mi++)
#pragma unroll
        for (int ni = 0; ni < 8; ni++)
#pragma unroll
            for (int ri = 0; ri < 2; ri++) {
                int m = m0 + wm + mi*16 + g + ri*8;
                int o = n0 + wn + ni*8 + 2*t;
                float v0 = acc[mi][ni][ri*2+0] * scl;
                float v1 = acc[mi][ni][ri*2+1] * scl;
                if (mode == 0) {
                    __half* dst = (blockIdx.z == 0) ? g_qh : (blockIdx.z == 1) ? g_kh : g_vh;
                    int b = m >> 10, nn = m & 1023, h = o >> 6, d = o & 63;
                    *(__half2*)(dst + ((size_t)((b*NH + h)*SEQ + nn))*HD + d) =
                        __floats2half2_rn(v0, v1);
                } else {
                    float* p = Cout + (size_t)m * FEAT + o;
                    p[0] = v0 + bias[o]; p[1] = v1 + bias[o+1];
                }
            }
}

// =====================================================================
// passR: outv[row] = f( sum_col exp2(A_row . B_col) * wcol )
// passA: (q', k, null, g_r, 0) -> r_i ; passB: (k, q', g_r, g_w, 1) -> w_j
// ldmatrix fragment feeds.
// =====================================================================
__global__ void __launch_bounds__(256, 2) passR_kernel(
    const __half* __restrict__ Ag, const __half* __restrict__ Bg,
    const float* __restrict__ colw, float* __restrict__ outv, int recip)
{
    extern __shared__ __half sh[];
    __half (*Qs)[72] = (__half (*)[72])sh;                  // [128][72]
    __half* KsB = sh + 128*72;                              // [2][128][72]
    __half2* wh2 = (__half2*)(sh + 3*128*72);               // [512]
    float* red = (float*)(wh2 + 512);                       // [128][2]

    int bh = blockIdx.y, i0 = blockIdx.x * 128;
    int tid = threadIdx.x;
    int warp = tid >> 5, lane = tid & 31;
    int g = lane >> 2, t = lane & 3;
    int wm = (warp >> 1) * 32, wn = (warp & 1) * 64;
    const __half* Ab = Ag + (size_t)bh*SEQ*HD;
    const __half* Bb = Bg + (size_t)bh*SEQ*HD;

    int arow = (lane & 15), acol8 = (lane >> 4) * 8;
    int brow = (lane & 7) + ((lane >> 4) & 1) * 8, bcol8 = ((lane >> 3) & 1) * 8;

    {   // A tile once
        int lr = tid >> 1, lc = (tid & 1) * 32;
        const __half* src = Ab + (size_t)(i0 + lr)*HD + lc;
        *(uint4*)&Qs[lr][lc+0]  = *(const uint4*)(src+0);
        *(uint4*)&Qs[lr][lc+8]  = *(const uint4*)(src+8);
        *(uint4*)&Qs[lr][lc+16] = *(const uint4*)(src+16);
        *(uint4*)&Qs[lr][lc+24] = *(const uint4*)(src+24);
    }
    if (colw) {   // preload all 1024 column weights as fp16 reciprocals
        const float* cw = colw + (size_t)bh*SEQ;
#pragma unroll
        for (int q = 0; q < 2; q++) {
            int idx = tid + q*256;
            wh2[idx] = __floats2half2_rn(1.f / cw[2*idx], 1.f / cw[2*idx+1]);
        }
    }

    auto loadK = [&](int s, int j0) {
        __half* Ks = KsB + s * 128*72;
#pragma unroll
        for (int q = 0; q < 4; q++) {
            int c = tid*4 + q;
            int row = c >> 3, off = (c & 7) * 8;
            CPA16(sptr(Ks + row*72 + off), Bb + (size_t)(j0+row)*HD + off);
        }
    };
    loadK(0, 0);   CPCOMMIT();
    loadK(1, 128); CPCOMMIT();

    float rs[2][2] = {{0.f,0.f},{0.f,0.f}};

    for (int jt = 0; jt < 8; jt++) {
        int j0 = jt * 128, st = jt & 1;
        const __half* Ks = KsB + st * 128*72;
        CPWAIT(1); __syncthreads();

        float acc[2][8][4];
#pragma unroll
        for (int mi = 0; mi < 2; mi++)
#pragma unroll
            for (int ni = 0; ni < 8; ni++)
#pragma unroll
                for (int c = 0; c < 4; c++) acc[mi][ni][c] = 0.f;

#pragma unroll
        for (int kk = 0; kk < 64; kk += 16) {
            unsigned a[2][4];
#pragma unroll
            for (int mi = 0; mi < 2; mi++)
                ldsm_x4(a[mi][0], a[mi][1], a[mi][2], a[mi][3],
                        sptr(&Qs[wm + mi*16 + arow][kk + acol8]));
#pragma unroll
            for (int np = 0; np < 4; np++) {
                unsigned b0, b1, b2, b3;
                ldsm_x4(b0, b1, b2, b3,
                        sptr(Ks + (wn + np*16 + brow)*72 + kk + bcol8));
                unsigned bb0[2] = {b0, b1}, bb1[2] = {b2, b3};
#pragma unroll
                for (int mi = 0; mi < 2; mi++) {
                    mma_f16(acc[mi][np*2+0], a[mi], bb0);
                    mma_f16(acc[mi][np*2+1], a[mi], bb1);
                }
            }
        }
        __syncthreads();                  // all warps done with Ks[st]
        if (jt + 2 < 8) loadK(st, (jt+2)*128);
        CPCOMMIT();

        // epilogue (overlaps the async loads): exp2 in fp16x2
#pragma unroll
        for (int mi = 0; mi < 2; mi++)
#pragma unroll
            for (int ri = 0; ri < 2; ri++) {
                float sum = 0.f;
#pragma unroll
                for (int ni = 0; ni < 8; ni++) {
                    int c0 = wn + ni*8 + 2*t;
                    __half2 hx = h2exp2(__floats2half2_rn(
                        acc[mi][ni][ri*2+0], acc[mi][ni][ri*2+1]));
                    if (colw) hx = __hmul2(hx, wh2[(j0 + c0) >> 1]);
                    float2 f = __half22float2(hx);
                    sum += f.x + f.y;
                }
                rs[mi][ri] += sum;
            }
    }

#pragma unroll
    for (int mi = 0; mi < 2; mi++)
#pragma unroll
        for (int ri = 0; ri < 2; ri++) {
            float v = rs[mi][ri];
            v += __shfl_xor_sync(0xffffffffu, v, 1);
            v += __shfl_xor_sync(0xffffffffu, v, 2);
            if (t == 0) red[(wm + mi*16 + g + ri*8)*2 + (warp & 1)] = v;
        }
    __syncthreads();
    if (tid < 128) {
        float s = red[tid*2] + red[tid*2 + 1];
        outv[(size_t)bh*SEQ + i0 + tid] = recip ? (1.f / s) : s;
    }
}

// =====================================================================
// passC (flash-style): out_i = (1/n)(sum_j e^{dots} w_j v_j)/(sum_j e^{dots} w_j)
// Q A-fragments hoisted across j-tiles; ldmatrix everywhere.
// =====================================================================
#define CSTG (2*128*72)   // K + V per stage
__global__ void __launch_bounds__(256, 2) passC_kernel()
{
    extern __shared__ __half sh[];
    __half (*Qs)[72] = (__half (*)[72])sh;                  // [128][72]
    __half* KVs = sh + 128*72;                              // [2][K|V]
    __half2* wh2 = (__half2*)(sh + 128*72 + 2*CSTG);        // [512]

    int bh = blockIdx.y;
    int b = bh / NH, h = bh % NH;
    int i0 = blockIdx.x * 128;
    int tid = threadIdx.x;
    int warp = tid >> 5, lane = tid & 31;
    int g = lane >> 2, t = lane & 3;
    int wm = warp * 16;

    const __half* Qb = g_qh + (size_t)bh*SEQ*HD;
    const __half* Kb = g_kh + (size_t)bh*SEQ*HD;
    const __half* Vb = g_vh + (size_t)bh*SEQ*HD;
    const float* wg = g_w + (size_t)bh*SEQ;

    int arow = (lane & 15), acol8 = (lane >> 4) * 8;
    int brow = (lane & 7) + ((lane >> 4) & 1) * 8, bcol8 = ((lane >> 3) & 1) * 8;

    {   // Q tile once
        int lr = tid >> 1, lc = (tid & 1) * 32;
        const __half* src = Qb + (size_t)(i0 + lr)*HD + lc;
        *(uint4*)&Qs[lr][lc+0]  = *(const uint4*)(src+0);
        *(uint4*)&Qs[lr][lc+8]  = *(const uint4*)(src+8);
        *(uint4*)&Qs[lr][lc+16] = *(const uint4*)(src+16);
        *(uint4*)&Qs[lr][lc+24] = *(const uint4*)(src+24);
    }
    {   // preload all 1024 w as fp16
#pragma unroll
        for (int q = 0; q < 2; q++) {
            int idx = tid + q*256;
            wh2[idx] = __floats2half2_rn(wg[2*idx], wg[2*idx+1]);
        }
    }

    auto loadKV = [&](int s, int j0) {
        __half* Ks = KVs + s * CSTG;
        __half* Vs = Ks + 128*72;
#pragma unroll
        for (int q = 0; q < 4; q++) {
            int c = tid*4 + q;
            int row = c >> 3, off = (c & 7) * 8;
            CPA16(sptr(Ks + row*72 + off), Kb + (size_t)(j0+row)*HD + off);
            CPA16(sptr(Vs + row*72 + off), Vb + (size_t)(j0+row)*HD + off);
        }
    };
    loadKV(0, 0);   CPCOMMIT();
    loadKV(1, 128); CPCOMMIT();

    __syncthreads();   // Qs visible to all warps

    // hoist Q A-fragments (invariant over j-tiles): 4 k-chunks x 4 regs
    unsigned afr[4][4];
#pragma unroll
    for (int kc = 0; kc < 4; kc++)
        ldsm_x4(afr[kc][0], afr[kc][1], afr[kc][2], afr[kc][3],
                sptr(&Qs[wm + arow][kc*16 + acol8]));

    float oacc[8][4];
#pragma unroll
    for (int nd = 0; nd < 8; nd++)
#pragma unroll
        for (int c = 0; c < 4; c++) oacc[nd][c] = 0.f;
    float den0 = 0.f, den1 = 0.f;

    for (int jt = 0; jt < 8; jt++) {
        int j0 = jt * 128, st = jt & 1;
        const __half* Ks = KVs + st * CSTG;
        const __half* Vs = Ks + 128*72;
        CPWAIT(1); __syncthreads();

#pragma unroll
        for (int half = 0; half < 2; half++) {
            const __half* Ksh = Ks + (half*64)*72;

            // S = Q K^T  (16 rows x 64 cols per warp)
            float sacc[8][4];
#pragma unroll
            for (int ni = 0; ni < 8; ni++)
#pragma unroll
                for (int c = 0; c < 4; c++) sacc[ni][c] = 0.f;

#pragma unroll
            for (int kc = 0; kc < 4; kc++) {
#pragma unroll
                for (int np = 0; np < 4; np++) {
                    unsigned b0, b1, b2, b3;
                    ldsm_x4(b0, b1, b2, b3,
                            sptr(Ksh + (np*16 + brow)*72 + kc*16 + bcol8));
                    unsigned bb0[2] = {b0, b1}, bb1[2] = {b2, b3};
                    mma_f16(sacc[np*2+0], afr[kc], bb0);
                    mma_f16(sacc[np*2+1], afr[kc], bb1);
                }
            }

            // P = exp2(S)*w in fp16 registers (A fragments) + denominator
            unsigned aP[4][4];
#pragma unroll
            for (int ni = 0; ni < 8; ni++) {
                int c0 = half*64 + ni*8 + 2*t;
                __half2 w2 = wh2[(j0 + c0) >> 1];
                __half2 hA = __hmul2(h2exp2(__floats2half2_rn(sacc[ni][0], sacc[ni][1])), w2);
                __half2 hB = __hmul2(h2exp2(__floats2half2_rn(sacc[ni][2], sacc[ni][3])), w2);
                float2 fa = __half22float2(hA), fb = __half22float2(hB);
                den0 += fa.x + fa.y; den1 += fb.x + fb.y;
                int kc = ni >> 1;
                if ((ni & 1) == 0) {
                    aP[kc][0] = *(unsigned*)&hA; aP[kc][1] = *(unsigned*)&hB;
                } else {
                    aP[kc][2] = *(unsigned*)&hA; aP[kc][3] = *(unsigned*)&hB;
                }
            }

            // O += P @ V^T  (B fragments via ldmatrix.trans on [j][d] tile)
            unsigned vbase = sptr(Vs + (half*64 + (lane & 15))*72);
#pragma unroll
            for (int kc = 0; kc < 4; kc++) {
                unsigned rowb = vbase + kc*16*144;   // 16 rows * 144 B/row
#pragma unroll
                for (int nd = 0; nd < 8; nd++) {
                    unsigned b0, b1;
                    ldsm_x2_t(b0, b1, rowb + nd*16);
                    unsigned bb[2] = {b0, b1};
                    mma_f16(oacc[nd], aP[kc], bb);
                }
            }
        }
        __syncthreads();   // all warps done with Ks/Vs[st]
        if (jt + 2 < 8) loadKV(st, (jt+2)*128);
        CPCOMMIT();
    }

    // normalize + write ctx (fp16, [b, n, h*64+d])
    den0 += __shfl_xor_sync(0xffffffffu, den0, 1);
    den0 += __shfl_xor_sync(0xffffffffu, den0, 2);
    den1 += __shfl_xor_sync(0xffffffffu, den1, 1);
    den1 += __shfl_xor_sync(0xffffffffu, den1, 2);
    const float inv_n = 1.f / (float)SEQ;
    float is0 = inv_n / den0, is1 = inv_n / den1;

    int row0 = i0 + wm + g, row1 = row0 + 8;
#pragma unroll
    for (int nd = 0; nd < 8; nd++) {
        int col = h*HD + nd*8 + 2*t;
        *(__half2*)(g_ctxh + ((size_t)(b*SEQ + row0))*FEAT + col) =
            __floats2half2_rn(oacc[nd][0]*is0, oacc[nd][1]*is0);
        *(__half2*)(g_ctxh + ((size_t)(b*SEQ + row1))*FEAT + col) =
            __floats2half2_rn(oacc[nd][2]*is1, oacc[nd][3]*is1);
    }
}

// =====================================================================
extern "C" void kernel_launch(void* const* d_in, const int* in_sizes, int n_in,
                              void* d_out, int out_size)
{
    const float* x  = (const float*)d_in[0];
    const float* Wq = (const float*)d_in[1];
    const float* Wk = (const float*)d_in[2];
    const float* Wv = (const float*)d_in[3];
    const float* Wo = (const float*)d_in[4];
    const float* bo = (const float*)d_in[5];
    float* out = (float*)d_out;

    const int gemm_smem  = 6 * GSTG * 2;                          // 61440
    const int passR_smem = 3*128*72*2 + 512*4 + 256*4;            // 58368
    const int passC_smem = (128*72 + 2*CSTG)*2 + 512*4;           // 94208
    cudaFuncSetAttribute(gemm_h_kernel, cudaFuncAttributeMaxDynamicSharedMemorySize, gemm_smem);
    cudaFuncSetAttribute(passR_kernel,  cudaFuncAttributeMaxDynamicSharedMemorySize, passR_smem);
    cudaFuncSetAttribute(passC_kernel,  cudaFuncAttributeMaxDynamicSharedMemorySize, passC_smem);

    __half *xh, *wh, *ctxh, *qp, *kp;
    float *rp, *wp;
    cudaGetSymbolAddress((void**)&xh,   g_xh);
    cudaGetSymbolAddress((void**)&wh,   g_wh);
    cudaGetSymbolAddress((void**)&ctxh, g_ctxh);
    cudaGetSymbolAddress((void**)&qp,   g_qh);
    cudaGetSymbolAddress((void**)&kp,   g_kh);
    cudaGetSymbolAddress((void**)&rp,   g_r);
    cudaGetSymbolAddress((void**)&wp,   g_w);

    // 0) fp32 -> fp16 copies
    {
        int nx4 = Bsz*SEQ*FEAT/4;
        int nw4 = FEAT*FEAT/4;
        cvt_kernel<<<(nx4+255)/256, 256>>>((const float4*)x, (__half2*)xh, nx4);
        cvtW_kernel<<<dim3((nw4+255)/256, 4), 256>>>(
            (const float4*)Wq, (const float4*)Wk, (const float4*)Wv, (const float4*)Wo,
            (__half2*)wh, nw4);
    }

    // 1) QKV projection -> fp16 q'(pre-scaled)/k/v
    gemm_h_kernel<<<dim3(FEAT/128, (Bsz*SEQ)/128, 3), 256, gemm_smem>>>(
        xh, wh, nullptr, nullptr, 0);

    dim3 ag(SEQ/128, BHN);
    // 2) r_i = sum_j e^{dots_ij}
    passR_kernel<<<ag, 256, passR_smem>>>(qp, kp, nullptr, rp, 0);
    // 3) w_j = 1 / sum_i e^{dots_ij} / r_i
    passR_kernel<<<ag, 256, passR_smem>>>(kp, qp, rp, wp, 1);
    // 4) ctx (flash-style, register P, ldmatrix everywhere)
    passC_kernel<<<ag, 256, passC_smem>>>();
    // 5) out = ctx @ Wo^T + bo
    gemm_h_kernel<<<dim3(FEAT/128, (Bsz*SEQ)/128, 1), 256, gemm_smem>>>(
        ctxh, wh + (size_t)3*FEAT*FEAT, bo, out, 1);
}